// round 10
// baseline (speedup 1.0000x reference)
#include <cuda_runtime.h>
#include <cuda_fp16.h>
#include <cstdint>
#include <math.h>

#define MAXN 100000
#define IN_DIM 512

// ---------------- scratch ----------------------------------------------------
__device__ __half g_bufH[MAXN * 64];   // support matrices (gathered operand, fp16)
__device__ float  g_bufF[MAXN * 64];   // spmm outputs (fp32)
__device__ int    g_rp[MAXN + 1];
__device__ float  g_stats[384];        // 3 layers x (64 sum + 64 sumsq)

// ---------------- row_ptr (sorted edge_row) + full stats zeroing -------------
__global__ void build_rowptr(const int* __restrict__ erow, int E, int n, int* __restrict__ rp) {
    if (blockIdx.x == 0) {
        for (int k = threadIdx.x; k < 384; k += blockDim.x) g_stats[k] = 0.f;
    }
    int i = blockIdx.x * blockDim.x + threadIdx.x;
    if (i > n) return;
    int lo = 0, hi = E;
    while (lo < hi) { int mid = (lo + hi) >> 1; if (erow[mid] < i) lo = mid + 1; else hi = mid; }
    rp[i] = lo;
}

// ---------------- HMMA m16n8k16 fp16 -> fp32 ---------------------------------
__device__ __forceinline__ void mma16816(float* c, uint32_t a0, uint32_t a1,
                                         uint32_t a2, uint32_t a3,
                                         uint32_t b0, uint32_t b1) {
    asm volatile(
        "mma.sync.aligned.m16n8k16.row.col.f32.f16.f16.f32 "
        "{%0,%1,%2,%3}, {%4,%5,%6,%7}, {%8,%9}, {%0,%1,%2,%3};"
        : "+f"(c[0]), "+f"(c[1]), "+f"(c[2]), "+f"(c[3])
        : "r"(a0), "r"(a1), "r"(a2), "r"(a3), "r"(b0), "r"(b1));
}

// ---------------- GEMM1: [M,512]x[512,64] via HMMA, A split hi+lo ------------
// Block: 128 rows x 64 cols, 8 warps (4m x 2n), K chunked by 64.
// launch_bounds (256,2): 128-reg cap so the 32 accumulators DON'T spill.
__global__ void __launch_bounds__(256, 2) gemm1_hmma(
    const float* __restrict__ A, const float* __restrict__ B,
    __half* __restrict__ C, int M) {
    __shared__ __half sAhi[128][72];
    __shared__ __half sAlo[128][72];
    __shared__ __half sB[64][72];      // transposed: [n][k]

    int tid = threadIdx.x;
    int wid = tid >> 5, lane = tid & 31;
    int wm = wid & 3, wn = wid >> 2;
    int rowBase = blockIdx.x * 128;
    int r = lane >> 2;                 // groupID 0..7
    int cq = (lane & 3) * 2;           // 2*tig: 0,2,4,6

    float acc[2][4][4];
#pragma unroll
    for (int mt = 0; mt < 2; ++mt)
#pragma unroll
        for (int nt = 0; nt < 4; ++nt)
#pragma unroll
            for (int i = 0; i < 4; ++i) acc[mt][nt][i] = 0.f;

    for (int kt = 0; kt < 512; kt += 64) {
        // load A chunk: 128 rows x 64 k (fp32 -> hi/lo fp16)
#pragma unroll
        for (int i = 0; i < 8; ++i) {
            int idx = tid + i * 256;
            int row = idx >> 4, c4 = (idx & 15) * 4;
            int grow = rowBase + row;
            float4 v = make_float4(0.f, 0.f, 0.f, 0.f);
            if (grow < M) v = *(const float4*)(A + (size_t)grow * 512 + kt + c4);
            __half h0 = __float2half_rn(v.x), h1 = __float2half_rn(v.y);
            __half h2 = __float2half_rn(v.z), h3 = __float2half_rn(v.w);
            __half2 hi01 = __halves2half2(h0, h1), hi23 = __halves2half2(h2, h3);
            __half2 lo01 = __floats2half2_rn(v.x - __half2float(h0), v.y - __half2float(h1));
            __half2 lo23 = __floats2half2_rn(v.z - __half2float(h2), v.w - __half2float(h3));
            *(__half2*)&sAhi[row][c4]     = hi01;
            *(__half2*)&sAhi[row][c4 + 2] = hi23;
            *(__half2*)&sAlo[row][c4]     = lo01;
            *(__half2*)&sAlo[row][c4 + 2] = lo23;
        }
        // load B chunk transposed: B[kt+k][n] -> sB[n][k]  (full 64 k rows)
#pragma unroll
        for (int i = 0; i < 4; ++i) {
            int idx = tid + i * 256;
            int k = idx >> 4, n4 = (idx & 15) * 4;
            float4 v = *(const float4*)(B + (size_t)(kt + k) * 64 + n4);
            sB[n4 + 0][k] = __float2half_rn(v.x);
            sB[n4 + 1][k] = __float2half_rn(v.y);
            sB[n4 + 2][k] = __float2half_rn(v.z);
            sB[n4 + 3][k] = __float2half_rn(v.w);
        }
        __syncthreads();

#pragma unroll
        for (int ks = 0; ks < 4; ++ks) {
            int c = cq + ks * 16;
            uint32_t bh[4][2];
#pragma unroll
            for (int nt = 0; nt < 4; ++nt) {
                int col = wn * 32 + nt * 8 + r;
                bh[nt][0] = *(const uint32_t*)&sB[col][c];
                bh[nt][1] = *(const uint32_t*)&sB[col][c + 8];
            }
#pragma unroll
            for (int mt = 0; mt < 2; ++mt) {
                int m = wm * 32 + mt * 16;
                uint32_t ah0 = *(const uint32_t*)&sAhi[m + r][c];
                uint32_t ah1 = *(const uint32_t*)&sAhi[m + r + 8][c];
                uint32_t ah2 = *(const uint32_t*)&sAhi[m + r][c + 8];
                uint32_t ah3 = *(const uint32_t*)&sAhi[m + r + 8][c + 8];
                uint32_t al0 = *(const uint32_t*)&sAlo[m + r][c];
                uint32_t al1 = *(const uint32_t*)&sAlo[m + r + 8][c];
                uint32_t al2 = *(const uint32_t*)&sAlo[m + r][c + 8];
                uint32_t al3 = *(const uint32_t*)&sAlo[m + r + 8][c + 8];
#pragma unroll
                for (int nt = 0; nt < 4; ++nt) {
                    mma16816(acc[mt][nt], ah0, ah1, ah2, ah3, bh[nt][0], bh[nt][1]);
                    mma16816(acc[mt][nt], al0, al1, al2, al3, bh[nt][0], bh[nt][1]);
                }
            }
        }
        __syncthreads();
    }

    // epilogue: fp16 output
#pragma unroll
    for (int mt = 0; mt < 2; ++mt) {
        int row0 = rowBase + wm * 32 + mt * 16 + r;
        int row1 = row0 + 8;
#pragma unroll
        for (int nt = 0; nt < 4; ++nt) {
            int col = wn * 32 + nt * 8 + cq;
            if (row0 < M)
                *(__half2*)(C + (size_t)row0 * 64 + col) =
                    __floats2half2_rn(acc[mt][nt][0], acc[mt][nt][1]);
            if (row1 < M)
                *(__half2*)(C + (size_t)row1 * 64 + col) =
                    __floats2half2_rn(acc[mt][nt][2], acc[mt][nt][3]);
        }
    }
}

// ---------------- fp16 gather helper ----------------------------------------
__device__ __forceinline__ void fma_half8(float* acc, uint4 raw, float v) {
    float2 f;
    f = __half22float2(*(__half2*)&raw.x); acc[0] = fmaf(v, f.x, acc[0]); acc[1] = fmaf(v, f.y, acc[1]);
    f = __half22float2(*(((__half2*)&raw.x) + 1)); acc[2] = fmaf(v, f.x, acc[2]); acc[3] = fmaf(v, f.y, acc[3]);
    f = __half22float2(*(__half2*)&raw.z); acc[4] = fmaf(v, f.x, acc[4]); acc[5] = fmaf(v, f.y, acc[5]);
    f = __half22float2(*(((__half2*)&raw.z) + 1)); acc[6] = fmaf(v, f.x, acc[6]); acc[7] = fmaf(v, f.y, acc[7]);
}

// ---------------- SpMM: half supports, float outputs, edge-prefetched --------
// Generic pattern per lane group: prefetch (ecol,ev) for iteration i+1 while
// gathering iteration i, so the 2-load dependent chain becomes 1 gather deep.
__global__ void __launch_bounds__(256) spmm64h(
    const __half* __restrict__ sup, const int* __restrict__ ecol,
    const float* __restrict__ ev, const int* __restrict__ rp,
    float* __restrict__ out, int n) {
    int gw = (blockIdx.x * blockDim.x + threadIdx.x) >> 5;
    int lane = threadIdx.x & 31;
    if (gw >= n) return;
    int s = rp[gw], e = rp[gw + 1];
    int g = lane >> 3, sl = lane & 7;
    float acc[8] = {0.f, 0.f, 0.f, 0.f, 0.f, 0.f, 0.f, 0.f};
    int j = s + g;
    if (j < e) {
        int c = ecol[j]; float v = ev[j];
        while (true) {
            int jn = j + 4;
            int cn = 0; float vn = 0.f;
            bool more = jn < e;
            if (more) { cn = ecol[jn]; vn = ev[jn]; }
            uint4 raw = *(const uint4*)(sup + (size_t)c * 64 + sl * 8);
            fma_half8(acc, raw, v);
            if (!more) break;
            j = jn; c = cn; v = vn;
        }
    }
#pragma unroll
    for (int o = 16; o >= 8; o >>= 1)
#pragma unroll
        for (int i = 0; i < 8; ++i) acc[i] += __shfl_down_sync(0xffffffffu, acc[i], o);
    if (lane < 8) {
        float* op = out + (size_t)gw * 64 + lane * 8;
        *(float4*)op       = make_float4(acc[0], acc[1], acc[2], acc[3]);
        *(float4*)(op + 4) = make_float4(acc[4], acc[5], acc[6], acc[7]);
    }
}

__global__ void __launch_bounds__(256) spmm32h(
    const __half* __restrict__ sup, const int* __restrict__ ecol,
    const float* __restrict__ ev, const int* __restrict__ rp,
    float* __restrict__ out, int n) {
    int gw = (blockIdx.x * blockDim.x + threadIdx.x) >> 5;
    int lane = threadIdx.x & 31;
    if (gw >= n) return;
    int s = rp[gw], e = rp[gw + 1];
    int g = lane >> 2, sl = lane & 3;
    float acc[8] = {0.f, 0.f, 0.f, 0.f, 0.f, 0.f, 0.f, 0.f};
    int j = s + g;
    if (j < e) {
        int c = ecol[j]; float v = ev[j];
        while (true) {
            int jn = j + 8;
            int cn = 0; float vn = 0.f;
            bool more = jn < e;
            if (more) { cn = ecol[jn]; vn = ev[jn]; }
            uint4 raw = *(const uint4*)(sup + (size_t)c * 32 + sl * 8);
            fma_half8(acc, raw, v);
            if (!more) break;
            j = jn; c = cn; v = vn;
        }
    }
#pragma unroll
    for (int o = 16; o >= 4; o >>= 1)
#pragma unroll
        for (int i = 0; i < 8; ++i) acc[i] += __shfl_down_sync(0xffffffffu, acc[i], o);
    if (lane < 4) {
        float* op = out + (size_t)gw * 32 + lane * 8;
        *(float4*)op       = make_float4(acc[0], acc[1], acc[2], acc[3]);
        *(float4*)(op + 4) = make_float4(acc[4], acc[5], acc[6], acc[7]);
    }
}

__global__ void __launch_bounds__(256) spmm16h(
    const __half* __restrict__ sup, const int* __restrict__ ecol,
    const float* __restrict__ ev, const int* __restrict__ rp,
    float* __restrict__ out, int n) {
    int gw = (blockIdx.x * blockDim.x + threadIdx.x) >> 5;
    int lane = threadIdx.x & 31;
    if (gw >= n) return;
    int s = rp[gw], e = rp[gw + 1];
    int g = lane >> 1, sl = lane & 1;
    float acc[8] = {0.f, 0.f, 0.f, 0.f, 0.f, 0.f, 0.f, 0.f};
    int j = s + g;
    if (j < e) {
        int c = ecol[j]; float v = ev[j];
        while (true) {
            int jn = j + 16;
            int cn = 0; float vn = 0.f;
            bool more = jn < e;
            if (more) { cn = ecol[jn]; vn = ev[jn]; }
            uint4 raw = *(const uint4*)(sup + (size_t)c * 16 + sl * 8);
            fma_half8(acc, raw, v);
            if (!more) break;
            j = jn; c = cn; v = vn;
        }
    }
#pragma unroll
    for (int o = 16; o >= 2; o >>= 1)
#pragma unroll
        for (int i = 0; i < 8; ++i) acc[i] += __shfl_down_sync(0xffffffffu, acc[i], o);
    if (lane < 2) {
        float* op = out + (size_t)gw * 16 + lane * 8;
        *(float4*)op       = make_float4(acc[0], acc[1], acc[2], acc[3]);
        *(float4*)(op + 4) = make_float4(acc[4], acc[5], acc[6], acc[7]);
    }
}

// ---------------- column stats: float4 reads, one flush per block ------------
template <int D>
__global__ void __launch_bounds__(256) col_stats(const float* __restrict__ h, int n, int layer) {
    const int S4 = D / 4;
    const int REPS = 256 / S4;
    __shared__ float s_sum[D], s_sq[D];
    int tid = threadIdx.x;
    if (tid < D) { s_sum[tid] = 0.f; s_sq[tid] = 0.f; }
    __syncthreads();
    int ch4 = tid % S4, rep = tid / S4;
    float4 s = make_float4(0.f, 0.f, 0.f, 0.f);
    float4 q = make_float4(0.f, 0.f, 0.f, 0.f);
    for (int r = blockIdx.x * REPS + rep; r < n; r += gridDim.x * REPS) {
        float4 v = *(const float4*)(h + (size_t)r * D + ch4 * 4);
        s.x += v.x; s.y += v.y; s.z += v.z; s.w += v.w;
        q.x = fmaf(v.x, v.x, q.x); q.y = fmaf(v.y, v.y, q.y);
        q.z = fmaf(v.z, v.z, q.z); q.w = fmaf(v.w, v.w, q.w);
    }
    atomicAdd(&s_sum[ch4 * 4 + 0], s.x); atomicAdd(&s_sq[ch4 * 4 + 0], q.x);
    atomicAdd(&s_sum[ch4 * 4 + 1], s.y); atomicAdd(&s_sq[ch4 * 4 + 1], q.y);
    atomicAdd(&s_sum[ch4 * 4 + 2], s.z); atomicAdd(&s_sq[ch4 * 4 + 2], q.z);
    atomicAdd(&s_sum[ch4 * 4 + 3], s.w); atomicAdd(&s_sq[ch4 * 4 + 3], q.w);
    __syncthreads();
    if (tid < D) {
        atomicAdd(&g_stats[layer * 128 + tid], s_sum[tid]);
        atomicAdd(&g_stats[layer * 128 + 64 + tid], s_sq[tid]);
    }
}

// ---------------- persistent fused BN+ELU + small GEMM, fp16 output ----------
template <int IN, int OUT>
__global__ void __launch_bounds__(256) gemm_small_fused(
    const float* __restrict__ h, const float* __restrict__ W,
    const float* __restrict__ gamma, const float* __restrict__ beta,
    int layer, __half* __restrict__ out, int n) {
    __shared__ float Ws[IN * OUT];
    __shared__ float sc[IN], sh[IN];
    int tid = threadIdx.x;
    for (int i = tid; i < IN * OUT; i += blockDim.x) Ws[i] = W[i];
    if (tid < IN) {
        float invn = 1.0f / (float)n;
        float mean = g_stats[layer * 128 + tid] * invn;
        float var  = g_stats[layer * 128 + 64 + tid] * invn - mean * mean;
        float k    = rsqrtf(var + 1e-5f) * gamma[tid];
        sc[tid] = k;
        sh[tid] = beta[tid] - mean * k;
    }
    __syncthreads();
    int wid = tid >> 5, lane = tid & 31;
    for (int node = blockIdx.x * 8 + wid; node < n; node += gridDim.x * 8) {
        const float* hr = h + (size_t)node * IN;
        float acc0 = 0.f;
#pragma unroll
        for (int k = 0; k < IN; k += 4) {
            float4 h4 = *(const float4*)(hr + k);
            float y0 = fmaf(h4.x, sc[k + 0], sh[k + 0]);
            float y1 = fmaf(h4.y, sc[k + 1], sh[k + 1]);
            float y2 = fmaf(h4.z, sc[k + 2], sh[k + 2]);
            float y3 = fmaf(h4.w, sc[k + 3], sh[k + 3]);
            y0 = y0 > 0.f ? y0 : expm1f(y0);
            y1 = y1 > 0.f ? y1 : expm1f(y1);
            y2 = y2 > 0.f ? y2 : expm1f(y2);
            y3 = y3 > 0.f ? y3 : expm1f(y3);
            acc0 = fmaf(y0, Ws[(k + 0) * OUT + lane], acc0);
            acc0 = fmaf(y1, Ws[(k + 1) * OUT + lane], acc0);
            acc0 = fmaf(y2, Ws[(k + 2) * OUT + lane], acc0);
            acc0 = fmaf(y3, Ws[(k + 3) * OUT + lane], acc0);
        }
        if (lane < OUT) out[(size_t)node * OUT + lane] = __float2half_rn(acc0);
    }
}

// ---------------- standalone BN+ELU for D=16, fp16 output --------------------
__global__ void bn_elu16(const float* __restrict__ h, __half* __restrict__ out,
                         const float* __restrict__ gamma, const float* __restrict__ beta,
                         int n) {
    int i = blockIdx.x * blockDim.x + threadIdx.x;
    if (i >= n * 16) return;
    int ch = i & 15;
    float invn = 1.0f / (float)n;
    float mean = g_stats[256 + ch] * invn;
    float var  = g_stats[256 + 64 + ch] * invn - mean * mean;
    float k = rsqrtf(var + 1e-5f) * gamma[ch];
    float y = fmaf(h[i] - mean, k, beta[ch]);
    out[i] = __float2half_rn(y > 0.f ? y : expm1f(y));
}

// ---------------- final: [n,16]x[16,40] + log_softmax, persistent ------------
__global__ void __launch_bounds__(256) gemm40_lsm(
    const float* __restrict__ h, const float* __restrict__ W,
    float* __restrict__ out, int n) {
    __shared__ float Ws[16 * 40];
    int tid = threadIdx.x;
    for (int i = tid; i < 16 * 40; i += blockDim.x) Ws[i] = W[i];
    __syncthreads();
    int wid = tid >> 5, lane = tid & 31;
    for (int node = blockIdx.x * 8 + wid; node < n; node += gridDim.x * 8) {
        const float* hr = h + (size_t)node * 16;
        float acc0 = 0.f, acc1 = 0.f;
#pragma unroll
        for (int k = 0; k < 16; k += 4) {
            float4 h4 = *(const float4*)(hr + k);
            acc0 = fmaf(h4.x, Ws[(k + 0) * 40 + lane], acc0);
            acc0 = fmaf(h4.y, Ws[(k + 1) * 40 + lane], acc0);
            acc0 = fmaf(h4.z, Ws[(k + 2) * 40 + lane], acc0);
            acc0 = fmaf(h4.w, Ws[(k + 3) * 40 + lane], acc0);
            if (lane < 8) {
                acc1 = fmaf(h4.x, Ws[(k + 0) * 40 + 32 + lane], acc1);
                acc1 = fmaf(h4.y, Ws[(k + 1) * 40 + 32 + lane], acc1);
                acc1 = fmaf(h4.z, Ws[(k + 2) * 40 + 32 + lane], acc1);
                acc1 = fmaf(h4.w, Ws[(k + 3) * 40 + 32 + lane], acc1);
            }
        }
        float a1 = (lane < 8) ? acc1 : __int_as_float(0xff800000);
        float m = fmaxf(acc0, a1);
#pragma unroll
        for (int o = 16; o; o >>= 1) m = fmaxf(m, __shfl_xor_sync(0xffffffffu, m, o));
        float ssum = expf(acc0 - m) + ((lane < 8) ? expf(acc1 - m) : 0.f);
#pragma unroll
        for (int o = 16; o; o >>= 1) ssum += __shfl_xor_sync(0xffffffffu, ssum, o);
        float lse = logf(ssum) + m;
        out[(size_t)node * 40 + lane] = acc0 - lse;
        if (lane < 8) out[(size_t)node * 40 + 32 + lane] = acc1 - lse;
    }
}

// ---------------- launch ------------------------------------------------------
static inline int dg(long long t, int b) { return (int)((t + b - 1) / b); }

extern "C" void kernel_launch(void* const* d_in, const int* in_sizes, int n_in,
                              void* d_out, int out_size) {
    const float* x    = (const float*)d_in[0];
    const int*   erow = (const int*)d_in[1];
    const int*   ecol = (const int*)d_in[2];
    const float* ev   = (const float*)d_in[3];
    const float* W1   = (const float*)d_in[4];
    const float* W2   = (const float*)d_in[5];
    const float* W3   = (const float*)d_in[6];
    const float* W4   = (const float*)d_in[7];
    const float* g1   = (const float*)d_in[8];
    const float* b1   = (const float*)d_in[9];
    const float* g2   = (const float*)d_in[10];
    const float* b2   = (const float*)d_in[11];
    const float* g3   = (const float*)d_in[12];
    const float* b3   = (const float*)d_in[13];

    int n = in_sizes[0] / IN_DIM;
    int E = in_sizes[1];
    float* out = (float*)d_out;

    __half* hH; float* hF; int* rp;
    cudaGetSymbolAddress((void**)&hH, g_bufH);
    cudaGetSymbolAddress((void**)&hF, g_bufF);
    cudaGetSymbolAddress((void**)&rp, g_rp);

    const int TB = 256;
    const int PERS = 1184;
    const int STATS_BLOCKS = 592;

    build_rowptr<<<dg(n + 1, TB), TB>>>(erow, E, n, rp);

    // ---- layer 1: HMMA gemm -> spmm64 -> stats ----
    gemm1_hmma<<<dg(n, 128), 256>>>(x, W1, hH, n);
    spmm64h<<<dg((long long)n * 32, TB), TB>>>(hH, ecol, ev, rp, hF, n);
    col_stats<64><<<STATS_BLOCKS, 256>>>(hF, n, 0);

    // ---- layer 2 ----
    gemm_small_fused<64, 32><<<PERS, TB>>>(hF, W2, g1, b1, 0, hH, n);
    spmm32h<<<dg((long long)n * 32, TB), TB>>>(hH, ecol, ev, rp, hF, n);
    col_stats<32><<<STATS_BLOCKS, 256>>>(hF, n, 1);

    // ---- layer 3 ----
    gemm_small_fused<32, 16><<<PERS, TB>>>(hF, W3, g2, b2, 1, hH, n);
    spmm16h<<<dg((long long)n * 32, TB), TB>>>(hH, ecol, ev, rp, hF, n);
    col_stats<16><<<STATS_BLOCKS, 256>>>(hF, n, 2);

    // ---- layer 4 (commuted): bn+elu -> spmm16 -> gemm(16->40)+log_softmax ----
    bn_elu16<<<dg((long long)n * 16, TB), TB>>>(hF, hH, g3, b3, n);
    spmm16h<<<dg((long long)n * 32, TB), TB>>>(hH, ecol, ev, rp, hF, n);
    gemm40_lsm<<<PERS, TB>>>(hF, W4, out, n);
}

// round 11
// speedup vs baseline: 1.1043x; 1.1043x over previous
#include <cuda_runtime.h>
#include <cuda_fp16.h>
#include <cstdint>
#include <math.h>

#define MAXN 100000
#define IN_DIM 512

// ---------------- scratch ----------------------------------------------------
__device__ __half g_bufH[MAXN * 64];   // support matrices (gathered operand, fp16)
__device__ float  g_bufF[MAXN * 64];   // spmm outputs (fp32)
__device__ int    g_rp[MAXN + 1];
__device__ float  g_stats[384];        // 3 layers x (64 sum + 64 sumsq)
__device__ unsigned g_barCount = 0;    // grid barrier state (monotonic gen -> replay-safe)
__device__ unsigned g_barGen   = 0;

// ---------------- grid barrier (persistent kernel, all blocks resident) ------
__device__ __forceinline__ void grid_barrier() {
    __threadfence();                   // make this thread's global writes visible
    __syncthreads();
    if (threadIdx.x == 0) {
        volatile unsigned* vgen = &g_barGen;
        unsigned gen = *vgen;
        unsigned arrived = atomicAdd(&g_barCount, 1u) + 1u;
        if (arrived == gridDim.x) {
            g_barCount = 0;
            __threadfence();
            *vgen = gen + 1u;
        } else {
            while (*vgen == gen) __nanosleep(64);
        }
    }
    __syncthreads();
    __threadfence();                   // acquire side
}

// ---------------- row_ptr (sorted edge_row) ----------------------------------
__global__ void build_rowptr(const int* __restrict__ erow, int E, int n, int* __restrict__ rp) {
    int i = blockIdx.x * blockDim.x + threadIdx.x;
    if (i > n) return;
    int lo = 0, hi = E;
    while (lo < hi) { int mid = (lo + hi) >> 1; if (erow[mid] < i) lo = mid + 1; else hi = mid; }
    rp[i] = lo;
}

// ---------------- HMMA m16n8k16 fp16 -> fp32 ---------------------------------
__device__ __forceinline__ void mma16816(float* c, uint32_t a0, uint32_t a1,
                                         uint32_t a2, uint32_t a3,
                                         uint32_t b0, uint32_t b1) {
    asm volatile(
        "mma.sync.aligned.m16n8k16.row.col.f32.f16.f16.f32 "
        "{%0,%1,%2,%3}, {%4,%5,%6,%7}, {%8,%9}, {%0,%1,%2,%3};"
        : "+f"(c[0]), "+f"(c[1]), "+f"(c[2]), "+f"(c[3])
        : "r"(a0), "r"(a1), "r"(a2), "r"(a3), "r"(b0), "r"(b1));
}

// ---------------- GEMM1: [M,512]x[512,64] via HMMA, A split hi+lo ------------
__global__ void __launch_bounds__(256, 2) gemm1_hmma(
    const float* __restrict__ A, const float* __restrict__ B,
    __half* __restrict__ C, int M) {
    __shared__ __half sAhi[128][72];
    __shared__ __half sAlo[128][72];
    __shared__ __half sB[64][72];      // transposed: [n][k]

    int tid = threadIdx.x;
    int wid = tid >> 5, lane = tid & 31;
    int wm = wid & 3, wn = wid >> 2;
    int rowBase = blockIdx.x * 128;
    int r = lane >> 2;
    int cq = (lane & 3) * 2;

    float acc[2][4][4];
#pragma unroll
    for (int mt = 0; mt < 2; ++mt)
#pragma unroll
        for (int nt = 0; nt < 4; ++nt)
#pragma unroll
            for (int i = 0; i < 4; ++i) acc[mt][nt][i] = 0.f;

    for (int kt = 0; kt < 512; kt += 64) {
#pragma unroll
        for (int i = 0; i < 8; ++i) {
            int idx = tid + i * 256;
            int row = idx >> 4, c4 = (idx & 15) * 4;
            int grow = rowBase + row;
            float4 v = make_float4(0.f, 0.f, 0.f, 0.f);
            if (grow < M) v = *(const float4*)(A + (size_t)grow * 512 + kt + c4);
            __half h0 = __float2half_rn(v.x), h1 = __float2half_rn(v.y);
            __half h2 = __float2half_rn(v.z), h3 = __float2half_rn(v.w);
            *(__half2*)&sAhi[row][c4]     = __halves2half2(h0, h1);
            *(__half2*)&sAhi[row][c4 + 2] = __halves2half2(h2, h3);
            *(__half2*)&sAlo[row][c4]     = __floats2half2_rn(v.x - __half2float(h0), v.y - __half2float(h1));
            *(__half2*)&sAlo[row][c4 + 2] = __floats2half2_rn(v.z - __half2float(h2), v.w - __half2float(h3));
        }
#pragma unroll
        for (int i = 0; i < 4; ++i) {
            int idx = tid + i * 256;
            int k = idx >> 4, n4 = (idx & 15) * 4;
            float4 v = *(const float4*)(B + (size_t)(kt + k) * 64 + n4);
            sB[n4 + 0][k] = __float2half_rn(v.x);
            sB[n4 + 1][k] = __float2half_rn(v.y);
            sB[n4 + 2][k] = __float2half_rn(v.z);
            sB[n4 + 3][k] = __float2half_rn(v.w);
        }
        __syncthreads();

#pragma unroll
        for (int ks = 0; ks < 4; ++ks) {
            int c = cq + ks * 16;
            uint32_t bh[4][2];
#pragma unroll
            for (int nt = 0; nt < 4; ++nt) {
                int col = wn * 32 + nt * 8 + r;
                bh[nt][0] = *(const uint32_t*)&sB[col][c];
                bh[nt][1] = *(const uint32_t*)&sB[col][c + 8];
            }
#pragma unroll
            for (int mt = 0; mt < 2; ++mt) {
                int m = wm * 32 + mt * 16;
                uint32_t ah0 = *(const uint32_t*)&sAhi[m + r][c];
                uint32_t ah1 = *(const uint32_t*)&sAhi[m + r + 8][c];
                uint32_t ah2 = *(const uint32_t*)&sAhi[m + r][c + 8];
                uint32_t ah3 = *(const uint32_t*)&sAhi[m + r + 8][c + 8];
                uint32_t al0 = *(const uint32_t*)&sAlo[m + r][c];
                uint32_t al1 = *(const uint32_t*)&sAlo[m + r + 8][c];
                uint32_t al2 = *(const uint32_t*)&sAlo[m + r][c + 8];
                uint32_t al3 = *(const uint32_t*)&sAlo[m + r + 8][c + 8];
#pragma unroll
                for (int nt = 0; nt < 4; ++nt) {
                    mma16816(acc[mt][nt], ah0, ah1, ah2, ah3, bh[nt][0], bh[nt][1]);
                    mma16816(acc[mt][nt], al0, al1, al2, al3, bh[nt][0], bh[nt][1]);
                }
            }
        }
        __syncthreads();
    }

#pragma unroll
    for (int mt = 0; mt < 2; ++mt) {
        int row0 = rowBase + wm * 32 + mt * 16 + r;
        int row1 = row0 + 8;
#pragma unroll
        for (int nt = 0; nt < 4; ++nt) {
            int col = wn * 32 + nt * 8 + cq;
            if (row0 < M)
                *(__half2*)(C + (size_t)row0 * 64 + col) =
                    __floats2half2_rn(acc[mt][nt][0], acc[mt][nt][1]);
            if (row1 < M)
                *(__half2*)(C + (size_t)row1 * 64 + col) =
                    __floats2half2_rn(acc[mt][nt][2], acc[mt][nt][3]);
        }
    }
}

// ---------------- fp16 gather helper ----------------------------------------
__device__ __forceinline__ void fma_half8(float* acc, uint4 raw, float v) {
    float2 f;
    f = __half22float2(*(__half2*)&raw.x); acc[0] = fmaf(v, f.x, acc[0]); acc[1] = fmaf(v, f.y, acc[1]);
    f = __half22float2(*(((__half2*)&raw.x) + 1)); acc[2] = fmaf(v, f.x, acc[2]); acc[3] = fmaf(v, f.y, acc[3]);
    f = __half22float2(*(__half2*)&raw.z); acc[4] = fmaf(v, f.x, acc[4]); acc[5] = fmaf(v, f.y, acc[5]);
    f = __half22float2(*(((__half2*)&raw.z) + 1)); acc[6] = fmaf(v, f.x, acc[6]); acc[7] = fmaf(v, f.y, acc[7]);
}

// ---------------- SpMM stage (persistent, warp per node, grid-stride) --------
// D elems/row; GRP lanes per group; STRIDE = 32/GRP edges in flight.
template <int D, int GRP>
__device__ void spmm_stage(const __half* __restrict__ sup, const int* __restrict__ ecol,
                           const float* __restrict__ ev, const int* __restrict__ rp,
                           float* __restrict__ out, int n) {
    const int STRIDE = 32 / GRP;                  // lane groups per warp
    int tid = threadIdx.x, wid = tid >> 5, lane = tid & 31;
    int g = lane / GRP, sl = lane % GRP;          // group id, slot in group
    int nwarps = gridDim.x * 8;
    for (int node = blockIdx.x * 8 + wid; node < n; node += nwarps) {
        int s = rp[node], e = rp[node + 1];
        float acc[8] = {0.f, 0.f, 0.f, 0.f, 0.f, 0.f, 0.f, 0.f};
        int j = s + g;
        if (j < e) {
            int c = ecol[j]; float v = ev[j];
            while (true) {
                int jn = j + STRIDE;
                int cn = 0; float vn = 0.f;
                bool more = jn < e;
                if (more) { cn = ecol[jn]; vn = ev[jn]; }
                uint4 raw = *(const uint4*)(sup + (size_t)c * D + sl * 8);
                fma_half8(acc, raw, v);
                if (!more) break;
                j = jn; c = cn; v = vn;
            }
        }
#pragma unroll
        for (int o = 16; o >= GRP; o >>= 1)
#pragma unroll
            for (int i = 0; i < 8; ++i) acc[i] += __shfl_down_sync(0xffffffffu, acc[i], o);
        if (lane < GRP) {
            float* op = out + (size_t)node * D + lane * 8;
            *(float4*)op       = make_float4(acc[0], acc[1], acc[2], acc[3]);
            *(float4*)(op + 4) = make_float4(acc[4], acc[5], acc[6], acc[7]);
        }
    }
}

// ---------------- column stats stage -----------------------------------------
template <int D>
__device__ void col_stats_stage(const float* __restrict__ h, int n, int layer,
                                float* s_sum, float* s_sq) {
    const int S4 = D / 4;
    const int REPS = 256 / S4;
    int tid = threadIdx.x;
    if (tid < D) { s_sum[tid] = 0.f; s_sq[tid] = 0.f; }
    __syncthreads();
    int ch4 = tid % S4, rep = tid / S4;
    float4 s = make_float4(0.f, 0.f, 0.f, 0.f);
    float4 q = make_float4(0.f, 0.f, 0.f, 0.f);
    for (int r = blockIdx.x * REPS + rep; r < n; r += gridDim.x * REPS) {
        float4 v = *(const float4*)(h + (size_t)r * D + ch4 * 4);
        s.x += v.x; s.y += v.y; s.z += v.z; s.w += v.w;
        q.x = fmaf(v.x, v.x, q.x); q.y = fmaf(v.y, v.y, q.y);
        q.z = fmaf(v.z, v.z, q.z); q.w = fmaf(v.w, v.w, q.w);
    }
    atomicAdd(&s_sum[ch4 * 4 + 0], s.x); atomicAdd(&s_sq[ch4 * 4 + 0], q.x);
    atomicAdd(&s_sum[ch4 * 4 + 1], s.y); atomicAdd(&s_sq[ch4 * 4 + 1], q.y);
    atomicAdd(&s_sum[ch4 * 4 + 2], s.z); atomicAdd(&s_sq[ch4 * 4 + 2], q.z);
    atomicAdd(&s_sum[ch4 * 4 + 3], s.w); atomicAdd(&s_sq[ch4 * 4 + 3], q.w);
    __syncthreads();
    if (tid < D) {
        atomicAdd(&g_stats[layer * 128 + tid], s_sum[tid]);
        atomicAdd(&g_stats[layer * 128 + 64 + tid], s_sq[tid]);
    }
    __syncthreads();
}

// ---------------- fused BN+ELU + small GEMM stage ----------------------------
template <int IN, int OUT>
__device__ void gemm_small_stage(const float* __restrict__ h, const float* __restrict__ W,
                                 const float* __restrict__ gamma, const float* __restrict__ beta,
                                 int layer, __half* __restrict__ out, int n,
                                 float* sWs, float* sc, float* sh) {
    int tid = threadIdx.x;
    for (int i = tid; i < IN * OUT; i += 256) sWs[i] = W[i];
    if (tid < IN) {
        float invn = 1.0f / (float)n;
        float mean = g_stats[layer * 128 + tid] * invn;
        float var  = g_stats[layer * 128 + 64 + tid] * invn - mean * mean;
        float k    = rsqrtf(var + 1e-5f) * gamma[tid];
        sc[tid] = k;
        sh[tid] = beta[tid] - mean * k;
    }
    __syncthreads();
    int wid = tid >> 5, lane = tid & 31;
    for (int node = blockIdx.x * 8 + wid; node < n; node += gridDim.x * 8) {
        const float* hr = h + (size_t)node * IN;
        float acc0 = 0.f;
#pragma unroll
        for (int k = 0; k < IN; k += 4) {
            float4 h4 = *(const float4*)(hr + k);
            float y0 = fmaf(h4.x, sc[k + 0], sh[k + 0]);
            float y1 = fmaf(h4.y, sc[k + 1], sh[k + 1]);
            float y2 = fmaf(h4.z, sc[k + 2], sh[k + 2]);
            float y3 = fmaf(h4.w, sc[k + 3], sh[k + 3]);
            y0 = y0 > 0.f ? y0 : expm1f(y0);
            y1 = y1 > 0.f ? y1 : expm1f(y1);
            y2 = y2 > 0.f ? y2 : expm1f(y2);
            y3 = y3 > 0.f ? y3 : expm1f(y3);
            acc0 = fmaf(y0, sWs[(k + 0) * OUT + lane], acc0);
            acc0 = fmaf(y1, sWs[(k + 1) * OUT + lane], acc0);
            acc0 = fmaf(y2, sWs[(k + 2) * OUT + lane], acc0);
            acc0 = fmaf(y3, sWs[(k + 3) * OUT + lane], acc0);
        }
        if (lane < OUT) out[(size_t)node * OUT + lane] = __float2half_rn(acc0);
    }
    __syncthreads();
}

// ---------------- THE persistent kernel: everything after gemm1 --------------
__global__ void __launch_bounds__(256, 4) fused_rest(
    __half* __restrict__ hH, float* __restrict__ hF,
    const int* __restrict__ ecol, const float* __restrict__ ev, const int* __restrict__ rp,
    const float* __restrict__ W2, const float* __restrict__ W3, const float* __restrict__ W4,
    const float* __restrict__ g1, const float* __restrict__ b1,
    const float* __restrict__ g2, const float* __restrict__ b2,
    const float* __restrict__ g3, const float* __restrict__ b3,
    float* __restrict__ out, int n) {
    __shared__ float sWs[64 * 32];       // largest weight tile (8KB); reused every stage
    __shared__ float sA[64], sB2[64];

    int tid = threadIdx.x;

    // S0: zero stats (block 0) + spmm64 (hH -> hF)
    if (blockIdx.x == 0) {
        for (int k = tid; k < 384; k += 256) g_stats[k] = 0.f;
    }
    spmm_stage<64, 8>(hH, ecol, ev, rp, hF, n);
    grid_barrier();

    // S1: stats layer0
    col_stats_stage<64>(hF, n, 0, sA, sB2);
    grid_barrier();

    // S2: bn0+elu+gemm 64->32  (hF -> hH)
    gemm_small_stage<64, 32>(hF, W2, g1, b1, 0, hH, n, sWs, sA, sB2);
    grid_barrier();

    // S3: spmm32 (hH -> hF)
    spmm_stage<32, 4>(hH, ecol, ev, rp, hF, n);
    grid_barrier();

    // S4: stats layer1
    col_stats_stage<32>(hF, n, 1, sA, sB2);
    grid_barrier();

    // S5: bn1+elu+gemm 32->16 (hF -> hH)
    gemm_small_stage<32, 16>(hF, W3, g2, b2, 1, hH, n, sWs, sA, sB2);
    grid_barrier();

    // S6: spmm16 (hH -> hF)
    spmm_stage<16, 2>(hH, ecol, ev, rp, hF, n);
    grid_barrier();

    // S7: stats layer2
    col_stats_stage<16>(hF, n, 2, sA, sB2);
    grid_barrier();

    // S8: bn2+elu (hF -> hH), elementwise
    {
        float invn = 1.0f / (float)n;
        for (int i = blockIdx.x * 256 + tid; i < n * 16; i += gridDim.x * 256) {
            int ch = i & 15;
            float mean = g_stats[256 + ch] * invn;
            float var  = g_stats[256 + 64 + ch] * invn - mean * mean;
            float k = rsqrtf(var + 1e-5f) * g3[ch];
            float y = fmaf(hF[i] - mean, k, b3[ch]);
            hH[i] = __float2half_rn(y > 0.f ? y : expm1f(y));
        }
    }
    grid_barrier();

    // S9: spmm16 layer4 (hH -> hF)
    spmm_stage<16, 2>(hH, ecol, ev, rp, hF, n);
    grid_barrier();

    // S10: gemm 16->40 + log_softmax (hF -> out)
    {
        for (int i = tid; i < 16 * 40; i += 256) sWs[i] = W4[i];
        __syncthreads();
        int wid = tid >> 5, lane = tid & 31;
        for (int node = blockIdx.x * 8 + wid; node < n; node += gridDim.x * 8) {
            const float* hr = hF + (size_t)node * 16;
            float acc0 = 0.f, acc1 = 0.f;
#pragma unroll
            for (int k = 0; k < 16; k += 4) {
                float4 h4 = *(const float4*)(hr + k);
                acc0 = fmaf(h4.x, sWs[(k + 0) * 40 + lane], acc0);
                acc0 = fmaf(h4.y, sWs[(k + 1) * 40 + lane], acc0);
                acc0 = fmaf(h4.z, sWs[(k + 2) * 40 + lane], acc0);
                acc0 = fmaf(h4.w, sWs[(k + 3) * 40 + lane], acc0);
                if (lane < 8) {
                    acc1 = fmaf(h4.x, sWs[(k + 0) * 40 + 32 + lane], acc1);
                    acc1 = fmaf(h4.y, sWs[(k + 1) * 40 + 32 + lane], acc1);
                    acc1 = fmaf(h4.z, sWs[(k + 2) * 40 + 32 + lane], acc1);
                    acc1 = fmaf(h4.w, sWs[(k + 3) * 40 + 32 + lane], acc1);
                }
            }
            float a1 = (lane < 8) ? acc1 : __int_as_float(0xff800000);
            float m = fmaxf(acc0, a1);
#pragma unroll
            for (int o = 16; o; o >>= 1) m = fmaxf(m, __shfl_xor_sync(0xffffffffu, m, o));
            float ssum = expf(acc0 - m) + ((lane < 8) ? expf(acc1 - m) : 0.f);
#pragma unroll
            for (int o = 16; o; o >>= 1) ssum += __shfl_xor_sync(0xffffffffu, ssum, o);
            float lse = logf(ssum) + m;
            out[(size_t)node * 40 + lane] = acc0 - lse;
            if (lane < 8) out[(size_t)node * 40 + 32 + lane] = acc1 - lse;
        }
    }
}

// ---------------- launch ------------------------------------------------------
static inline int dg(long long t, int b) { return (int)((t + b - 1) / b); }

extern "C" void kernel_launch(void* const* d_in, const int* in_sizes, int n_in,
                              void* d_out, int out_size) {
    const float* x    = (const float*)d_in[0];
    const int*   erow = (const int*)d_in[1];
    const int*   ecol = (const int*)d_in[2];
    const float* ev   = (const float*)d_in[3];
    const float* W1   = (const float*)d_in[4];
    const float* W2   = (const float*)d_in[5];
    const float* W3   = (const float*)d_in[6];
    const float* W4   = (const float*)d_in[7];
    const float* g1   = (const float*)d_in[8];
    const float* b1   = (const float*)d_in[9];
    const float* g2   = (const float*)d_in[10];
    const float* b2   = (const float*)d_in[11];
    const float* g3   = (const float*)d_in[12];
    const float* b3   = (const float*)d_in[13];

    int n = in_sizes[0] / IN_DIM;
    int E = in_sizes[1];
    float* out = (float*)d_out;

    __half* hH; float* hF; int* rp;
    cudaGetSymbolAddress((void**)&hH, g_bufH);
    cudaGetSymbolAddress((void**)&hF, g_bufF);
    cudaGetSymbolAddress((void**)&rp, g_rp);

    const int TB = 256;
    const int PERS = 148 * 4;   // exactly the co-resident capacity at launch_bounds(256,4)

    build_rowptr<<<dg(n + 1, TB), TB>>>(erow, E, n, rp);
    gemm1_hmma<<<dg(n, 128), 256>>>(x, W1, hH, n);
    fused_rest<<<PERS, TB>>>(hH, hF, ecol, ev, rp, W2, W3, W4,
                             g1, b1, g2, b2, g3, b3, out, n);
}

// round 12
// speedup vs baseline: 1.8290x; 1.6563x over previous
#include <cuda_runtime.h>
#include <cuda_fp16.h>
#include <cstdint>
#include <math.h>

#define MAXN 100000
#define IN_DIM 512

// ---------------- scratch ----------------------------------------------------
__device__ __half g_bufH[MAXN * 64];   // support matrices (gathered operand, fp16)
__device__ float  g_bufF[MAXN * 64];   // spmm outputs (fp32)
__device__ int    g_rp[MAXN + 1];
__device__ float  g_stats[384];        // 3 layers x (64 sum + 64 sumsq)
__device__ unsigned g_barCount = 0;    // grid barrier state (monotonic gen -> replay-safe)
__device__ unsigned g_barGen   = 0;

// ---------------- grid barrier (persistent kernel, all blocks resident) ------
__device__ __forceinline__ void grid_barrier() {
    __threadfence();
    __syncthreads();
    if (threadIdx.x == 0) {
        volatile unsigned* vgen = &g_barGen;
        unsigned gen = *vgen;
        unsigned arrived = atomicAdd(&g_barCount, 1u) + 1u;
        if (arrived == gridDim.x) {
            g_barCount = 0;
            __threadfence();
            *vgen = gen + 1u;
        } else {
            while (*vgen == gen) __nanosleep(64);
        }
    }
    __syncthreads();
    __threadfence();
}

// ---------------- HMMA m16n8k16 fp16 -> fp32 ---------------------------------
__device__ __forceinline__ void mma16816(float* c, uint32_t a0, uint32_t a1,
                                         uint32_t a2, uint32_t a3,
                                         uint32_t b0, uint32_t b1) {
    asm volatile(
        "mma.sync.aligned.m16n8k16.row.col.f32.f16.f16.f32 "
        "{%0,%1,%2,%3}, {%4,%5,%6,%7}, {%8,%9}, {%0,%1,%2,%3};"
        : "+f"(c[0]), "+f"(c[1]), "+f"(c[2]), "+f"(c[3])
        : "r"(a0), "r"(a1), "r"(a2), "r"(a3), "r"(b0), "r"(b1));
}

// ---------------- GEMM1 + fused row_ptr build --------------------------------
__global__ void __launch_bounds__(256, 2) gemm1_hmma(
    const float* __restrict__ A, const float* __restrict__ B,
    __half* __restrict__ C, int M,
    const int* __restrict__ erow, int E, int* __restrict__ rp) {
    __shared__ __half sAhi[128][72];
    __shared__ __half sAlo[128][72];
    __shared__ __half sB[64][72];      // transposed: [n][k]

    int tid = threadIdx.x;

    // prologue: each block covers a slice of the rowptr binary searches
    {
        int i = blockIdx.x * 256 + tid;
        if (i <= M) {
            int lo = 0, hi = E;
            while (lo < hi) { int mid = (lo + hi) >> 1; if (erow[mid] < i) lo = mid + 1; else hi = mid; }
            rp[i] = lo;
        }
    }

    int wid = tid >> 5, lane = tid & 31;
    int wm = wid & 3, wn = wid >> 2;
    int rowBase = blockIdx.x * 128;
    int r = lane >> 2;
    int cq = (lane & 3) * 2;

    float acc[2][4][4];
#pragma unroll
    for (int mt = 0; mt < 2; ++mt)
#pragma unroll
        for (int nt = 0; nt < 4; ++nt)
#pragma unroll
            for (int i = 0; i < 4; ++i) acc[mt][nt][i] = 0.f;

    for (int kt = 0; kt < 512; kt += 64) {
#pragma unroll
        for (int i = 0; i < 8; ++i) {
            int idx = tid + i * 256;
            int row = idx >> 4, c4 = (idx & 15) * 4;
            int grow = rowBase + row;
            float4 v = make_float4(0.f, 0.f, 0.f, 0.f);
            if (grow < M) v = *(const float4*)(A + (size_t)grow * 512 + kt + c4);
            __half h0 = __float2half_rn(v.x), h1 = __float2half_rn(v.y);
            __half h2 = __float2half_rn(v.z), h3 = __float2half_rn(v.w);
            *(__half2*)&sAhi[row][c4]     = __halves2half2(h0, h1);
            *(__half2*)&sAhi[row][c4 + 2] = __halves2half2(h2, h3);
            *(__half2*)&sAlo[row][c4]     = __floats2half2_rn(v.x - __half2float(h0), v.y - __half2float(h1));
            *(__half2*)&sAlo[row][c4 + 2] = __floats2half2_rn(v.z - __half2float(h2), v.w - __half2float(h3));
        }
#pragma unroll
        for (int i = 0; i < 4; ++i) {
            int idx = tid + i * 256;
            int k = idx >> 4, n4 = (idx & 15) * 4;
            float4 v = *(const float4*)(B + (size_t)(kt + k) * 64 + n4);
            sB[n4 + 0][k] = __float2half_rn(v.x);
            sB[n4 + 1][k] = __float2half_rn(v.y);
            sB[n4 + 2][k] = __float2half_rn(v.z);
            sB[n4 + 3][k] = __float2half_rn(v.w);
        }
        __syncthreads();

#pragma unroll
        for (int ks = 0; ks < 4; ++ks) {
            int c = cq + ks * 16;
            uint32_t bh[4][2];
#pragma unroll
            for (int nt = 0; nt < 4; ++nt) {
                int col = wn * 32 + nt * 8 + r;
                bh[nt][0] = *(const uint32_t*)&sB[col][c];
                bh[nt][1] = *(const uint32_t*)&sB[col][c + 8];
            }
#pragma unroll
            for (int mt = 0; mt < 2; ++mt) {
                int m = wm * 32 + mt * 16;
                uint32_t ah0 = *(const uint32_t*)&sAhi[m + r][c];
                uint32_t ah1 = *(const uint32_t*)&sAhi[m + r + 8][c];
                uint32_t ah2 = *(const uint32_t*)&sAhi[m + r][c + 8];
                uint32_t ah3 = *(const uint32_t*)&sAhi[m + r + 8][c + 8];
                uint32_t al0 = *(const uint32_t*)&sAlo[m + r][c];
                uint32_t al1 = *(const uint32_t*)&sAlo[m + r + 8][c];
                uint32_t al2 = *(const uint32_t*)&sAlo[m + r][c + 8];
                uint32_t al3 = *(const uint32_t*)&sAlo[m + r + 8][c + 8];
#pragma unroll
                for (int nt = 0; nt < 4; ++nt) {
                    mma16816(acc[mt][nt], ah0, ah1, ah2, ah3, bh[nt][0], bh[nt][1]);
                    mma16816(acc[mt][nt], al0, al1, al2, al3, bh[nt][0], bh[nt][1]);
                }
            }
        }
        __syncthreads();
    }

#pragma unroll
    for (int mt = 0; mt < 2; ++mt) {
        int row0 = rowBase + wm * 32 + mt * 16 + r;
        int row1 = row0 + 8;
#pragma unroll
        for (int nt = 0; nt < 4; ++nt) {
            int col = wn * 32 + nt * 8 + cq;
            if (row0 < M)
                *(__half2*)(C + (size_t)row0 * 64 + col) =
                    __floats2half2_rn(acc[mt][nt][0], acc[mt][nt][1]);
            if (row1 < M)
                *(__half2*)(C + (size_t)row1 * 64 + col) =
                    __floats2half2_rn(acc[mt][nt][2], acc[mt][nt][3]);
        }
    }
}

// ---------------- fp16 gather helper ----------------------------------------
__device__ __forceinline__ void fma_half8(float* acc, uint4 raw, float v) {
    float2 f;
    f = __half22float2(*(__half2*)&raw.x); acc[0] = fmaf(v, f.x, acc[0]); acc[1] = fmaf(v, f.y, acc[1]);
    f = __half22float2(*(((__half2*)&raw.x) + 1)); acc[2] = fmaf(v, f.x, acc[2]); acc[3] = fmaf(v, f.y, acc[3]);
    f = __half22float2(*(__half2*)&raw.z); acc[4] = fmaf(v, f.x, acc[4]); acc[5] = fmaf(v, f.y, acc[5]);
    f = __half22float2(*(((__half2*)&raw.z) + 1)); acc[6] = fmaf(v, f.x, acc[6]); acc[7] = fmaf(v, f.y, acc[7]);
}

// ---------------- SpMM stage (persistent, warp per node, grid-stride) --------
template <int D, int GRP>
__device__ void spmm_stage(const __half* __restrict__ sup, const int* __restrict__ ecol,
                           const float* __restrict__ ev, const int* __restrict__ rp,
                           float* __restrict__ out, int n) {
    const int STRIDE = 32 / GRP;
    int tid = threadIdx.x, wid = tid >> 5, lane = tid & 31;
    int g = lane / GRP, sl = lane % GRP;
    int nwarps = gridDim.x * 8;
    for (int node = blockIdx.x * 8 + wid; node < n; node += nwarps) {
        int s = rp[node], e = rp[node + 1];
        float acc[8] = {0.f, 0.f, 0.f, 0.f, 0.f, 0.f, 0.f, 0.f};
        int j = s + g;
        if (j < e) {
            int c = ecol[j]; float v = ev[j];
            while (true) {
                int jn = j + STRIDE;
                int cn = 0; float vn = 0.f;
                bool more = jn < e;
                if (more) { cn = ecol[jn]; vn = ev[jn]; }
                uint4 raw = *(const uint4*)(sup + (size_t)c * D + sl * 8);
                fma_half8(acc, raw, v);
                if (!more) break;
                j = jn; c = cn; v = vn;
            }
        }
#pragma unroll
        for (int o = 16; o >= GRP; o >>= 1)
#pragma unroll
            for (int i = 0; i < 8; ++i) acc[i] += __shfl_down_sync(0xffffffffu, acc[i], o);
        if (lane < GRP) {
            float* op = out + (size_t)node * D + lane * 8;
            *(float4*)op       = make_float4(acc[0], acc[1], acc[2], acc[3]);
            *(float4*)(op + 4) = make_float4(acc[4], acc[5], acc[6], acc[7]);
        }
    }
}

// ---------------- column stats stage -----------------------------------------
template <int D>
__device__ void col_stats_stage(const float* __restrict__ h, int n, int layer,
                                float* s_sum, float* s_sq) {
    const int S4 = D / 4;
    const int REPS = 256 / S4;
    int tid = threadIdx.x;
    if (tid < D) { s_sum[tid] = 0.f; s_sq[tid] = 0.f; }
    __syncthreads();
    int ch4 = tid % S4, rep = tid / S4;
    float4 s = make_float4(0.f, 0.f, 0.f, 0.f);
    float4 q = make_float4(0.f, 0.f, 0.f, 0.f);
    for (int r = blockIdx.x * REPS + rep; r < n; r += gridDim.x * REPS) {
        float4 v = *(const float4*)(h + (size_t)r * D + ch4 * 4);
        s.x += v.x; s.y += v.y; s.z += v.z; s.w += v.w;
        q.x = fmaf(v.x, v.x, q.x); q.y = fmaf(v.y, v.y, q.y);
        q.z = fmaf(v.z, v.z, q.z); q.w = fmaf(v.w, v.w, q.w);
    }
    atomicAdd(&s_sum[ch4 * 4 + 0], s.x); atomicAdd(&s_sq[ch4 * 4 + 0], q.x);
    atomicAdd(&s_sum[ch4 * 4 + 1], s.y); atomicAdd(&s_sq[ch4 * 4 + 1], q.y);
    atomicAdd(&s_sum[ch4 * 4 + 2], s.z); atomicAdd(&s_sq[ch4 * 4 + 2], q.z);
    atomicAdd(&s_sum[ch4 * 4 + 3], s.w); atomicAdd(&s_sq[ch4 * 4 + 3], q.w);
    __syncthreads();
    if (tid < D) {
        atomicAdd(&g_stats[layer * 128 + tid], s_sum[tid]);
        atomicAdd(&g_stats[layer * 128 + 64 + tid], s_sq[tid]);
    }
    __syncthreads();
}

// ---------------- fused BN+ELU + small GEMM stage (shuffle broadcast) --------
// Lane l computes BN+ELU for element l (and l+32 if IN==64) ONCE; the FMA loop
// broadcasts y_k via shfl. ~5x fewer instructions than per-lane recompute.
template <int IN, int OUT>
__device__ void gemm_small_stage(const float* __restrict__ h, const float* __restrict__ W,
                                 const float* __restrict__ gamma, const float* __restrict__ beta,
                                 int layer, __half* __restrict__ out, int n,
                                 float* sWs, float* sc, float* sh) {
    int tid = threadIdx.x;
    for (int i = tid; i < IN * OUT; i += 256) sWs[i] = W[i];
    if (tid < IN) {
        float invn = 1.0f / (float)n;
        float mean = g_stats[layer * 128 + tid] * invn;
        float var  = g_stats[layer * 128 + 64 + tid] * invn - mean * mean;
        float k    = rsqrtf(var + 1e-5f) * gamma[tid];
        sc[tid] = k;
        sh[tid] = beta[tid] - mean * k;
    }
    __syncthreads();
    int wid = tid >> 5, lane = tid & 31;
    float scA = (lane < IN) ? sc[lane] : 0.f;
    float shA = (lane < IN) ? sh[lane] : 0.f;
    float scB = (IN == 64) ? sc[lane + 32] : 0.f;
    float shB = (IN == 64) ? sh[lane + 32] : 0.f;
    for (int node = blockIdx.x * 8 + wid; node < n; node += gridDim.x * 8) {
        const float* hr = h + (size_t)node * IN;
        float ya = 0.f, yb = 0.f;
        if (lane < IN) {
            float xv = hr[lane];
            ya = fmaf(xv, scA, shA);
            ya = ya > 0.f ? ya : (__expf(ya) - 1.0f);
        }
        if (IN == 64) {
            float xv = hr[lane + 32];
            yb = fmaf(xv, scB, shB);
            yb = yb > 0.f ? yb : (__expf(yb) - 1.0f);
        }
        float acc = 0.f;
        const int KA = (IN < 32) ? IN : 32;
#pragma unroll
        for (int k = 0; k < KA; ++k) {
            float yk = __shfl_sync(0xffffffffu, ya, k);
            acc = fmaf(yk, sWs[k * OUT + lane], acc);
        }
        if (IN == 64) {
#pragma unroll
            for (int k = 0; k < 32; ++k) {
                float yk = __shfl_sync(0xffffffffu, yb, k);
                acc = fmaf(yk, sWs[(k + 32) * OUT + lane], acc);
            }
        }
        if (lane < OUT) out[(size_t)node * OUT + lane] = __float2half_rn(acc);
    }
    __syncthreads();
}

// ---------------- THE persistent kernel: everything after gemm1 --------------
__global__ void __launch_bounds__(256, 4) fused_rest(
    __half* __restrict__ hH, float* __restrict__ hF,
    const int* __restrict__ ecol, const float* __restrict__ ev, const int* __restrict__ rp,
    const float* __restrict__ W2, const float* __restrict__ W3, const float* __restrict__ W4,
    const float* __restrict__ g1, const float* __restrict__ b1,
    const float* __restrict__ g2, const float* __restrict__ b2,
    const float* __restrict__ g3, const float* __restrict__ b3,
    float* __restrict__ out, int n) {
    __shared__ float sWs[64 * 32];
    __shared__ float sA[64], sB2[64];

    int tid = threadIdx.x;

    // S0: zero stats (block 0) + spmm64 (hH -> hF)
    if (blockIdx.x == 0) {
        for (int k = tid; k < 384; k += 256) g_stats[k] = 0.f;
    }
    spmm_stage<64, 8>(hH, ecol, ev, rp, hF, n);
    grid_barrier();

    // S1: stats layer0
    col_stats_stage<64>(hF, n, 0, sA, sB2);
    grid_barrier();

    // S2: bn0+elu+gemm 64->32  (hF -> hH)
    gemm_small_stage<64, 32>(hF, W2, g1, b1, 0, hH, n, sWs, sA, sB2);
    grid_barrier();

    // S3: spmm32 (hH -> hF)
    spmm_stage<32, 4>(hH, ecol, ev, rp, hF, n);
    grid_barrier();

    // S4: stats layer1
    col_stats_stage<32>(hF, n, 1, sA, sB2);
    grid_barrier();

    // S5: bn1+elu+gemm 32->16 (hF -> hH)
    gemm_small_stage<32, 16>(hF, W3, g2, b2, 1, hH, n, sWs, sA, sB2);
    grid_barrier();

    // S6: spmm16 (hH -> hF)
    spmm_stage<16, 2>(hH, ecol, ev, rp, hF, n);
    grid_barrier();

    // S7: stats layer2
    col_stats_stage<16>(hF, n, 2, sA, sB2);
    grid_barrier();

    // S8: bn2+elu (hF -> hH), elementwise
    {
        float invn = 1.0f / (float)n;
        for (int i = blockIdx.x * 256 + tid; i < n * 16; i += gridDim.x * 256) {
            int ch = i & 15;
            float mean = g_stats[256 + ch] * invn;
            float var  = g_stats[256 + 64 + ch] * invn - mean * mean;
            float k = rsqrtf(var + 1e-5f) * g3[ch];
            float y = fmaf(hF[i] - mean, k, b3[ch]);
            hH[i] = __float2half_rn(y > 0.f ? y : (__expf(y) - 1.0f));
        }
    }
    grid_barrier();

    // S9: spmm16 layer4 (hH -> hF)
    spmm_stage<16, 2>(hH, ecol, ev, rp, hF, n);
    grid_barrier();

    // S10: gemm 16->40 + log_softmax (hF -> out), shuffle-broadcast operand
    {
        for (int i = tid; i < 16 * 40; i += 256) sWs[i] = W4[i];
        __syncthreads();
        int wid = tid >> 5, lane = tid & 31;
        for (int node = blockIdx.x * 8 + wid; node < n; node += gridDim.x * 8) {
            const float* hr = hF + (size_t)node * 16;
            float ya = (lane < 16) ? hr[lane] : 0.f;
            float acc0 = 0.f, acc1 = 0.f;
#pragma unroll
            for (int k = 0; k < 16; ++k) {
                float yk = __shfl_sync(0xffffffffu, ya, k);
                acc0 = fmaf(yk, sWs[k * 40 + lane], acc0);
                if (lane < 8) acc1 = fmaf(yk, sWs[k * 40 + 32 + lane], acc1);
            }
            float a1 = (lane < 8) ? acc1 : __int_as_float(0xff800000);
            float m = fmaxf(acc0, a1);
#pragma unroll
            for (int o = 16; o; o >>= 1) m = fmaxf(m, __shfl_xor_sync(0xffffffffu, m, o));
            float ssum = expf(acc0 - m) + ((lane < 8) ? expf(acc1 - m) : 0.f);
#pragma unroll
            for (int o = 16; o; o >>= 1) ssum += __shfl_xor_sync(0xffffffffu, ssum, o);
            float lse = logf(ssum) + m;
            out[(size_t)node * 40 + lane] = acc0 - lse;
            if (lane < 8) out[(size_t)node * 40 + 32 + lane] = acc1 - lse;
        }
    }
}

// ---------------- launch ------------------------------------------------------
static inline int dg(long long t, int b) { return (int)((t + b - 1) / b); }

extern "C" void kernel_launch(void* const* d_in, const int* in_sizes, int n_in,
                              void* d_out, int out_size) {
    const float* x    = (const float*)d_in[0];
    const int*   erow = (const int*)d_in[1];
    const int*   ecol = (const int*)d_in[2];
    const float* ev   = (const float*)d_in[3];
    const float* W1   = (const float*)d_in[4];
    const float* W2   = (const float*)d_in[5];
    const float* W3   = (const float*)d_in[6];
    const float* W4   = (const float*)d_in[7];
    const float* g1   = (const float*)d_in[8];
    const float* b1   = (const float*)d_in[9];
    const float* g2   = (const float*)d_in[10];
    const float* b2   = (const float*)d_in[11];
    const float* g3   = (const float*)d_in[12];
    const float* b3   = (const float*)d_in[13];

    int n = in_sizes[0] / IN_DIM;
    int E = in_sizes[1];
    float* out = (float*)d_out;

    __half* hH; float* hF; int* rp;
    cudaGetSymbolAddress((void**)&hH, g_bufH);
    cudaGetSymbolAddress((void**)&hF, g_bufF);
    cudaGetSymbolAddress((void**)&rp, g_rp);

    const int PERS = 148 * 4;

    // gemm1 grid: max(gemm tiles, rowptr coverage)
    int gb = dg(n, 128);
    int rb = dg(n + 1, 256);
    int grid1 = gb > rb ? gb : rb;

    gemm1_hmma<<<grid1, 256>>>(x, W1, hH, n, erow, E, rp);
    fused_rest<<<PERS, 256>>>(hH, hF, ecol, ev, rp, W2, W3, W4,
                              g1, b1, g2, b2, g3, b3, out, n);
}

// round 13
// speedup vs baseline: 1.8702x; 1.0225x over previous
#include <cuda_runtime.h>
#include <cuda_fp16.h>
#include <cstdint>
#include <math.h>

#define MAXN 100000
#define IN_DIM 512

// ---------------- scratch ----------------------------------------------------
__device__ __half g_bufH[MAXN * 64];   // support matrices (gathered operand, fp16)
__device__ float  g_bufF[MAXN * 64];   // spmm outputs (fp32)
__device__ int    g_rp[MAXN + 1];
__device__ float  g_stats[384];        // 3 layers x (64 sum + 64 sumsq)
__device__ unsigned g_barCount = 0;    // grid barrier (monotonic gen -> replay-safe)
__device__ unsigned g_barGen   = 0;

// ---------------- grid barrier (persistent kernel, all blocks resident) ------
__device__ __forceinline__ void grid_barrier() {
    __threadfence();
    __syncthreads();
    if (threadIdx.x == 0) {
        volatile unsigned* vgen = &g_barGen;
        unsigned gen = *vgen;
        unsigned arrived = atomicAdd(&g_barCount, 1u) + 1u;
        if (arrived == gridDim.x) {
            g_barCount = 0;
            __threadfence();
            *vgen = gen + 1u;
        } else {
            while (*vgen == gen) __nanosleep(64);
        }
    }
    __syncthreads();
    __threadfence();
}

// ---------------- packed f32x2 FMA -------------------------------------------
__device__ __forceinline__ float2 ffma2(float2 a, float2 b, float2 c) {
    unsigned long long ua = *reinterpret_cast<unsigned long long*>(&a);
    unsigned long long ub = *reinterpret_cast<unsigned long long*>(&b);
    unsigned long long uc = *reinterpret_cast<unsigned long long*>(&c);
    unsigned long long ud;
    asm("fma.rn.f32x2 %0, %1, %2, %3;" : "=l"(ud) : "l"(ua), "l"(ub), "l"(uc));
    return *reinterpret_cast<float2*>(&ud);
}

// ---------------- HMMA m16n8k16 fp16 -> fp32 ---------------------------------
__device__ __forceinline__ void mma16816(float* c, uint32_t a0, uint32_t a1,
                                         uint32_t a2, uint32_t a3,
                                         uint32_t b0, uint32_t b1) {
    asm volatile(
        "mma.sync.aligned.m16n8k16.row.col.f32.f16.f16.f32 "
        "{%0,%1,%2,%3}, {%4,%5,%6,%7}, {%8,%9}, {%0,%1,%2,%3};"
        : "+f"(c[0]), "+f"(c[1]), "+f"(c[2]), "+f"(c[3])
        : "r"(a0), "r"(a1), "r"(a2), "r"(a3), "r"(b0), "r"(b1));
}

// ---------------- GEMM1 + fused row_ptr build + stats zeroing ----------------
__global__ void __launch_bounds__(256, 2) gemm1_hmma(
    const float* __restrict__ A, const float* __restrict__ B,
    __half* __restrict__ C, int M,
    const int* __restrict__ erow, int E, int* __restrict__ rp) {
    __shared__ __half sAhi[128][72];
    __shared__ __half sAlo[128][72];
    __shared__ __half sB[64][72];      // transposed: [n][k]

    int tid = threadIdx.x;

    // prologue: rowptr binary searches + stats zeroing (stream-ordered, replay-safe)
    {
        int i = blockIdx.x * 256 + tid;
        if (i <= M) {
            int lo = 0, hi = E;
            while (lo < hi) { int mid = (lo + hi) >> 1; if (erow[mid] < i) lo = mid + 1; else hi = mid; }
            rp[i] = lo;
        }
        if (blockIdx.x == 0) {
            for (int k = tid; k < 384; k += 256) g_stats[k] = 0.f;
        }
    }

    int wid = tid >> 5, lane = tid & 31;
    int wm = wid & 3, wn = wid >> 2;
    int rowBase = blockIdx.x * 128;
    int r = lane >> 2;
    int cq = (lane & 3) * 2;

    float acc[2][4][4];
#pragma unroll
    for (int mt = 0; mt < 2; ++mt)
#pragma unroll
        for (int nt = 0; nt < 4; ++nt)
#pragma unroll
            for (int i = 0; i < 4; ++i) acc[mt][nt][i] = 0.f;

    for (int kt = 0; kt < 512; kt += 64) {
#pragma unroll
        for (int i = 0; i < 8; ++i) {
            int idx = tid + i * 256;
            int row = idx >> 4, c4 = (idx & 15) * 4;
            int grow = rowBase + row;
            float4 v = make_float4(0.f, 0.f, 0.f, 0.f);
            if (grow < M) v = *(const float4*)(A + (size_t)grow * 512 + kt + c4);
            __half h0 = __float2half_rn(v.x), h1 = __float2half_rn(v.y);
            __half h2 = __float2half_rn(v.z), h3 = __float2half_rn(v.w);
            *(__half2*)&sAhi[row][c4]     = __halves2half2(h0, h1);
            *(__half2*)&sAhi[row][c4 + 2] = __halves2half2(h2, h3);
            *(__half2*)&sAlo[row][c4]     = __floats2half2_rn(v.x - __half2float(h0), v.y - __half2float(h1));
            *(__half2*)&sAlo[row][c4 + 2] = __floats2half2_rn(v.z - __half2float(h2), v.w - __half2float(h3));
        }
#pragma unroll
        for (int i = 0; i < 4; ++i) {
            int idx = tid + i * 256;
            int k = idx >> 4, n4 = (idx & 15) * 4;
            float4 v = *(const float4*)(B + (size_t)(kt + k) * 64 + n4);
            sB[n4 + 0][k] = __float2half_rn(v.x);
            sB[n4 + 1][k] = __float2half_rn(v.y);
            sB[n4 + 2][k] = __float2half_rn(v.z);
            sB[n4 + 3][k] = __float2half_rn(v.w);
        }
        __syncthreads();

#pragma unroll
        for (int ks = 0; ks < 4; ++ks) {
            int c = cq + ks * 16;
            uint32_t bh[4][2];
#pragma unroll
            for (int nt = 0; nt < 4; ++nt) {
                int col = wn * 32 + nt * 8 + r;
                bh[nt][0] = *(const uint32_t*)&sB[col][c];
                bh[nt][1] = *(const uint32_t*)&sB[col][c + 8];
            }
#pragma unroll
            for (int mt = 0; mt < 2; ++mt) {
                int m = wm * 32 + mt * 16;
                uint32_t ah0 = *(const uint32_t*)&sAhi[m + r][c];
                uint32_t ah1 = *(const uint32_t*)&sAhi[m + r + 8][c];
                uint32_t ah2 = *(const uint32_t*)&sAhi[m + r][c + 8];
                uint32_t ah3 = *(const uint32_t*)&sAhi[m + r + 8][c + 8];
                uint32_t al0 = *(const uint32_t*)&sAlo[m + r][c];
                uint32_t al1 = *(const uint32_t*)&sAlo[m + r + 8][c];
                uint32_t al2 = *(const uint32_t*)&sAlo[m + r][c + 8];
                uint32_t al3 = *(const uint32_t*)&sAlo[m + r + 8][c + 8];
#pragma unroll
                for (int nt = 0; nt < 4; ++nt) {
                    mma16816(acc[mt][nt], ah0, ah1, ah2, ah3, bh[nt][0], bh[nt][1]);
                    mma16816(acc[mt][nt], al0, al1, al2, al3, bh[nt][0], bh[nt][1]);
                }
            }
        }
        __syncthreads();
    }

#pragma unroll
    for (int mt = 0; mt < 2; ++mt) {
        int row0 = rowBase + wm * 32 + mt * 16 + r;
        int row1 = row0 + 8;
#pragma unroll
        for (int nt = 0; nt < 4; ++nt) {
            int col = wn * 32 + nt * 8 + cq;
            if (row0 < M)
                *(__half2*)(C + (size_t)row0 * 64 + col) =
                    __floats2half2_rn(acc[mt][nt][0], acc[mt][nt][1]);
            if (row1 < M)
                *(__half2*)(C + (size_t)row1 * 64 + col) =
                    __floats2half2_rn(acc[mt][nt][2], acc[mt][nt][3]);
        }
    }
}

// ---------------- fp16 gather helper (FFMA2, float2 accumulators) ------------
__device__ __forceinline__ void fma_half8(float2* acc, uint4 raw, float v) {
    float2 vv = make_float2(v, v);
    float2 f0 = __half22float2(*(__half2*)&raw.x);
    float2 f1 = __half22float2(*(((__half2*)&raw.x) + 1));
    float2 f2 = __half22float2(*(__half2*)&raw.z);
    float2 f3 = __half22float2(*(((__half2*)&raw.z) + 1));
    acc[0] = ffma2(vv, f0, acc[0]);
    acc[1] = ffma2(vv, f1, acc[1]);
    acc[2] = ffma2(vv, f2, acc[2]);
    acc[3] = ffma2(vv, f3, acc[3]);
}

// ---------------- SpMM stage: 2-edge unrolled gathers, warp per node ---------
template <int D, int GRP>
__device__ void spmm_stage(const __half* __restrict__ sup, const int* __restrict__ ecol,
                           const float* __restrict__ ev, const int* __restrict__ rp,
                           float* __restrict__ out, int n) {
    const int STRIDE = 32 / GRP;
    int tid = threadIdx.x, wid = tid >> 5, lane = tid & 31;
    int g = lane / GRP, sl = lane % GRP;
    int nwarps = gridDim.x * 8;
    for (int node = blockIdx.x * 8 + wid; node < n; node += nwarps) {
        int s = rp[node], e = rp[node + 1];
        float2 acc[4];
#pragma unroll
        for (int i = 0; i < 4; ++i) acc[i] = make_float2(0.f, 0.f);
        int j = s + g;
        for (; j + STRIDE < e; j += 2 * STRIDE) {
            int   c0 = ecol[j];          float v0 = ev[j];
            int   c1 = ecol[j + STRIDE]; float v1 = ev[j + STRIDE];
            uint4 r0 = *(const uint4*)(sup + (size_t)c0 * D + sl * 8);
            uint4 r1 = *(const uint4*)(sup + (size_t)c1 * D + sl * 8);
            fma_half8(acc, r0, v0);
            fma_half8(acc, r1, v1);
        }
        if (j < e) {
            int c = ecol[j]; float v = ev[j];
            uint4 raw = *(const uint4*)(sup + (size_t)c * D + sl * 8);
            fma_half8(acc, raw, v);
        }
#pragma unroll
        for (int o = 16; o >= GRP; o >>= 1)
#pragma unroll
            for (int i = 0; i < 4; ++i) {
                acc[i].x += __shfl_down_sync(0xffffffffu, acc[i].x, o);
                acc[i].y += __shfl_down_sync(0xffffffffu, acc[i].y, o);
            }
        if (lane < GRP) {
            float* op = out + (size_t)node * D + lane * 8;
            *(float4*)op       = make_float4(acc[0].x, acc[0].y, acc[1].x, acc[1].y);
            *(float4*)(op + 4) = make_float4(acc[2].x, acc[2].y, acc[3].x, acc[3].y);
        }
    }
}

// ---------------- column stats stage -----------------------------------------
template <int D>
__device__ void col_stats_stage(const float* __restrict__ h, int n, int layer,
                                float* s_sum, float* s_sq) {
    const int S4 = D / 4;
    const int REPS = 256 / S4;
    int tid = threadIdx.x;
    if (tid < D) { s_sum[tid] = 0.f; s_sq[tid] = 0.f; }
    __syncthreads();
    int ch4 = tid % S4, rep = tid / S4;
    float4 s = make_float4(0.f, 0.f, 0.f, 0.f);
    float4 q = make_float4(0.f, 0.f, 0.f, 0.f);
    for (int r = blockIdx.x * REPS + rep; r < n; r += gridDim.x * REPS) {
        float4 v = *(const float4*)(h + (size_t)r * D + ch4 * 4);
        s.x += v.x; s.y += v.y; s.z += v.z; s.w += v.w;
        q.x = fmaf(v.x, v.x, q.x); q.y = fmaf(v.y, v.y, q.y);
        q.z = fmaf(v.z, v.z, q.z); q.w = fmaf(v.w, v.w, q.w);
    }
    atomicAdd(&s_sum[ch4 * 4 + 0], s.x); atomicAdd(&s_sq[ch4 * 4 + 0], q.x);
    atomicAdd(&s_sum[ch4 * 4 + 1], s.y); atomicAdd(&s_sq[ch4 * 4 + 1], q.y);
    atomicAdd(&s_sum[ch4 * 4 + 2], s.z); atomicAdd(&s_sq[ch4 * 4 + 2], q.z);
    atomicAdd(&s_sum[ch4 * 4 + 3], s.w); atomicAdd(&s_sq[ch4 * 4 + 3], q.w);
    __syncthreads();
    if (tid < D) {
        atomicAdd(&g_stats[layer * 128 + tid], s_sum[tid]);
        atomicAdd(&g_stats[layer * 128 + 64 + tid], s_sq[tid]);
    }
    __syncthreads();
}

// ---------------- fused BN+ELU + small GEMM stage (shuffle broadcast) --------
template <int IN, int OUT>
__device__ void gemm_small_stage(const float* __restrict__ h, const float* __restrict__ W,
                                 const float* __restrict__ gamma, const float* __restrict__ beta,
                                 int layer, __half* __restrict__ out, int n,
                                 float* sWs, float* sc, float* sh) {
    int tid = threadIdx.x;
    for (int i = tid; i < IN * OUT; i += 256) sWs[i] = W[i];
    if (tid < IN) {
        float invn = 1.0f / (float)n;
        float mean = g_stats[layer * 128 + tid] * invn;
        float var  = g_stats[layer * 128 + 64 + tid] * invn - mean * mean;
        float k    = rsqrtf(var + 1e-5f) * gamma[tid];
        sc[tid] = k;
        sh[tid] = beta[tid] - mean * k;
    }
    __syncthreads();
    int wid = tid >> 5, lane = tid & 31;
    float scA = (lane < IN) ? sc[lane] : 0.f;
    float shA = (lane < IN) ? sh[lane] : 0.f;
    float scB = (IN == 64) ? sc[lane + 32] : 0.f;
    float shB = (IN == 64) ? sh[lane + 32] : 0.f;
    for (int node = blockIdx.x * 8 + wid; node < n; node += gridDim.x * 8) {
        const float* hr = h + (size_t)node * IN;
        float ya = 0.f, yb = 0.f;
        if (lane < IN) {
            float xv = hr[lane];
            ya = fmaf(xv, scA, shA);
            ya = ya > 0.f ? ya : (__expf(ya) - 1.0f);
        }
        if (IN == 64) {
            float xv = hr[lane + 32];
            yb = fmaf(xv, scB, shB);
            yb = yb > 0.f ? yb : (__expf(yb) - 1.0f);
        }
        float acc = 0.f;
        const int KA = (IN < 32) ? IN : 32;
#pragma unroll
        for (int k = 0; k < KA; ++k) {
            float yk = __shfl_sync(0xffffffffu, ya, k);
            acc = fmaf(yk, sWs[k * OUT + lane], acc);
        }
        if (IN == 64) {
#pragma unroll
            for (int k = 0; k < 32; ++k) {
                float yk = __shfl_sync(0xffffffffu, yb, k);
                acc = fmaf(yk, sWs[(k + 32) * OUT + lane], acc);
            }
        }
        if (lane < OUT) out[(size_t)node * OUT + lane] = __float2half_rn(acc);
    }
    __syncthreads();
}

// ---------------- THE persistent kernel: everything after gemm1 --------------
__global__ void __launch_bounds__(256, 4) fused_rest(
    __half* __restrict__ hH, float* __restrict__ hF,
    const int* __restrict__ ecol, const float* __restrict__ ev, const int* __restrict__ rp,
    const float* __restrict__ W2, const float* __restrict__ W3, const float* __restrict__ W4,
    const float* __restrict__ g1, const float* __restrict__ b1,
    const float* __restrict__ g2, const float* __restrict__ b2,
    const float* __restrict__ g3, const float* __restrict__ b3,
    float* __restrict__ out, int n) {
    __shared__ float sWs[64 * 32];
    __shared__ float sA[64], sB2[64];

    int tid = threadIdx.x;

    // S0: spmm64 (hH -> hF)
    spmm_stage<64, 8>(hH, ecol, ev, rp, hF, n);
    grid_barrier();

    // S1: stats layer0
    col_stats_stage<64>(hF, n, 0, sA, sB2);
    grid_barrier();

    // S2: bn0+elu+gemm 64->32  (hF -> hH)
    gemm_small_stage<64, 32>(hF, W2, g1, b1, 0, hH, n, sWs, sA, sB2);
    grid_barrier();

    // S3: spmm32 (hH -> hF)
    spmm_stage<32, 4>(hH, ecol, ev, rp, hF, n);
    grid_barrier();

    // S4: stats layer1
    col_stats_stage<32>(hF, n, 1, sA, sB2);
    grid_barrier();

    // S5: bn1+elu+gemm 32->16 (hF -> hH)
    gemm_small_stage<32, 16>(hF, W3, g2, b2, 1, hH, n, sWs, sA, sB2);
    grid_barrier();

    // S6: spmm16 (hH -> hF)
    spmm_stage<16, 2>(hH, ecol, ev, rp, hF, n);
    grid_barrier();

    // S7: stats layer2
    col_stats_stage<16>(hF, n, 2, sA, sB2);
    grid_barrier();

    // S8: bn2+elu (hF -> hH), elementwise
    {
        float invn = 1.0f / (float)n;
        for (int i = blockIdx.x * 256 + tid; i < n * 16; i += gridDim.x * 256) {
            int ch = i & 15;
            float mean = g_stats[256 + ch] * invn;
            float var  = g_stats[256 + 64 + ch] * invn - mean * mean;
            float k = rsqrtf(var + 1e-5f) * g3[ch];
            float y = fmaf(hF[i] - mean, k, b3[ch]);
            hH[i] = __float2half_rn(y > 0.f ? y : (__expf(y) - 1.0f));
        }
    }
    grid_barrier();

    // S9: FUSED final: spmm16 -> gemm(16->40) -> log_softmax (hH -> out)
    {
        for (int i = tid; i < 16 * 40; i += 256) sWs[i] = W4[i];
        __syncthreads();
        int wid = tid >> 5, lane = tid & 31;
        int g = lane >> 1, sl = lane & 1;       // GRP=2, STRIDE=16
        int nwarps = gridDim.x * 8;
        for (int node = blockIdx.x * 8 + wid; node < n; node += nwarps) {
            int s = rp[node], e = rp[node + 1];
            float2 acc[4];
#pragma unroll
            for (int i = 0; i < 4; ++i) acc[i] = make_float2(0.f, 0.f);
            int j = s + g;
            for (; j + 16 < e; j += 32) {
                int   c0 = ecol[j];      float v0 = ev[j];
                int   c1 = ecol[j + 16]; float v1 = ev[j + 16];
                uint4 r0 = *(const uint4*)(hH + (size_t)c0 * 16 + sl * 8);
                uint4 r1 = *(const uint4*)(hH + (size_t)c1 * 16 + sl * 8);
                fma_half8(acc, r0, v0);
                fma_half8(acc, r1, v1);
            }
            if (j < e) {
                int c = ecol[j]; float v = ev[j];
                uint4 raw = *(const uint4*)(hH + (size_t)c * 16 + sl * 8);
                fma_half8(acc, raw, v);
            }
#pragma unroll
            for (int o = 16; o >= 2; o >>= 1)
#pragma unroll
                for (int i = 0; i < 4; ++i) {
                    acc[i].x += __shfl_down_sync(0xffffffffu, acc[i].x, o);
                    acc[i].y += __shfl_down_sync(0xffffffffu, acc[i].y, o);
                }
            // lanes 0 (k=0..7) and 1 (k=8..15) hold the node's 16-vector.
            float acc0 = 0.f, acc1 = 0.f;
#pragma unroll
            for (int k = 0; k < 16; ++k) {
                float val = (k & 1) ? acc[(k & 7) >> 1].y : acc[(k & 7) >> 1].x;
                float yk = __shfl_sync(0xffffffffu, val, k >> 3);
                acc0 = fmaf(yk, sWs[k * 40 + lane], acc0);
                if (lane < 8) acc1 = fmaf(yk, sWs[k * 40 + 32 + lane], acc1);
            }
            float a1 = (lane < 8) ? acc1 : __int_as_float(0xff800000);
            float m = fmaxf(acc0, a1);
#pragma unroll
            for (int o = 16; o; o >>= 1) m = fmaxf(m, __shfl_xor_sync(0xffffffffu, m, o));
            float ssum = expf(acc0 - m) + ((lane < 8) ? expf(acc1 - m) : 0.f);
#pragma unroll
            for (int o = 16; o; o >>= 1) ssum += __shfl_xor_sync(0xffffffffu, ssum, o);
            float lse = logf(ssum) + m;
            out[(size_t)node * 40 + lane] = acc0 - lse;
            if (lane < 8) out[(size_t)node * 40 + 32 + lane] = acc1 - lse;
        }
    }
}

// ---------------- launch ------------------------------------------------------
static inline int dg(long long t, int b) { return (int)((t + b - 1) / b); }

extern "C" void kernel_launch(void* const* d_in, const int* in_sizes, int n_in,
                              void* d_out, int out_size) {
    const float* x    = (const float*)d_in[0];
    const int*   erow = (const int*)d_in[1];
    const int*   ecol = (const int*)d_in[2];
    const float* ev   = (const float*)d_in[3];
    const float* W1   = (const float*)d_in[4];
    const float* W2   = (const float*)d_in[5];
    const float* W3   = (const float*)d_in[6];
    const float* W4   = (const float*)d_in[7];
    const float* g1   = (const float*)d_in[8];
    const float* b1   = (const float*)d_in[9];
    const float* g2   = (const float*)d_in[10];
    const float* b2   = (const float*)d_in[11];
    const float* g3   = (const float*)d_in[12];
    const float* b3   = (const float*)d_in[13];

    int n = in_sizes[0] / IN_DIM;
    int E = in_sizes[1];
    float* out = (float*)d_out;

    __half* hH; float* hF; int* rp;
    cudaGetSymbolAddress((void**)&hH, g_bufH);
    cudaGetSymbolAddress((void**)&hF, g_bufF);
    cudaGetSymbolAddress((void**)&rp, g_rp);

    const int PERS = 148 * 4;

    int gb = dg(n, 128);
    int rb = dg(n + 1, 256);
    int grid1 = gb > rb ? gb : rb;

    gemm1_hmma<<<grid1, 256>>>(x, W1, hH, n, erow, E, rp);
    fused_rest<<<PERS, 256>>>(hH, hF, ecol, ev, rp, W2, W3, W4,
                              g1, b1, g2, b2, g3, b3, out, n);
}

// round 14
// speedup vs baseline: 1.8942x; 1.0128x over previous
#include <cuda_runtime.h>
#include <cuda_fp16.h>
#include <cstdint>
#include <math.h>

#define MAXN 100000
#define IN_DIM 512

// ---------------- scratch ----------------------------------------------------
__device__ __half g_bufH[MAXN * 64];   // support matrices (gathered operand, fp16)
__device__ float  g_bufF[MAXN * 64];   // spmm outputs (fp32)
__device__ int    g_rp[MAXN + 1];
__device__ float  g_stats[384];        // 3 layers x (64 sum + 64 sumsq)
__device__ unsigned g_barCount = 0;    // grid barrier (monotonic gen -> replay-safe)
__device__ unsigned g_barGen   = 0;

// ---------------- grid barrier (persistent kernel, all blocks resident) ------
__device__ __forceinline__ void grid_barrier() {
    __threadfence();
    __syncthreads();
    if (threadIdx.x == 0) {
        volatile unsigned* vgen = &g_barGen;
        unsigned gen = *vgen;
        unsigned arrived = atomicAdd(&g_barCount, 1u) + 1u;
        if (arrived == gridDim.x) {
            g_barCount = 0;
            __threadfence();
            *vgen = gen + 1u;
        } else {
            while (*vgen == gen) __nanosleep(64);
        }
    }
    __syncthreads();
    __threadfence();
}

// ---------------- packed f32x2 FMA -------------------------------------------
__device__ __forceinline__ float2 ffma2(float2 a, float2 b, float2 c) {
    unsigned long long ua = *reinterpret_cast<unsigned long long*>(&a);
    unsigned long long ub = *reinterpret_cast<unsigned long long*>(&b);
    unsigned long long uc = *reinterpret_cast<unsigned long long*>(&c);
    unsigned long long ud;
    asm("fma.rn.f32x2 %0, %1, %2, %3;" : "=l"(ud) : "l"(ua), "l"(ub), "l"(uc));
    return *reinterpret_cast<float2*>(&ud);
}

// ---------------- HMMA m16n8k16 fp16 -> fp32 ---------------------------------
__device__ __forceinline__ void mma16816(float* c, uint32_t a0, uint32_t a1,
                                         uint32_t a2, uint32_t a3,
                                         uint32_t b0, uint32_t b1) {
    asm volatile(
        "mma.sync.aligned.m16n8k16.row.col.f32.f16.f16.f32 "
        "{%0,%1,%2,%3}, {%4,%5,%6,%7}, {%8,%9}, {%0,%1,%2,%3};"
        : "+f"(c[0]), "+f"(c[1]), "+f"(c[2]), "+f"(c[3])
        : "r"(a0), "r"(a1), "r"(a2), "r"(a3), "r"(b0), "r"(b1));
}

// ---------------- GEMM1 + fused row_ptr build + stats zeroing ----------------
__global__ void __launch_bounds__(256, 3) gemm1_hmma(
    const float* __restrict__ A, const float* __restrict__ B,
    __half* __restrict__ C, int M,
    const int* __restrict__ erow, int E, int* __restrict__ rp) {
    __shared__ __half sAhi[128][72];
    __shared__ __half sAlo[128][72];
    __shared__ __half sB[64][72];      // transposed: [n][k]

    int tid = threadIdx.x;

    // prologue: rowptr binary searches + stats zeroing (stream-ordered, replay-safe)
    {
        int i = blockIdx.x * 256 + tid;
        if (i <= M) {
            int lo = 0, hi = E;
            while (lo < hi) { int mid = (lo + hi) >> 1; if (erow[mid] < i) lo = mid + 1; else hi = mid; }
            rp[i] = lo;
        }
        if (blockIdx.x == 0) {
            for (int k = tid; k < 384; k += 256) g_stats[k] = 0.f;
        }
    }

    int wid = tid >> 5, lane = tid & 31;
    int wm = wid & 3, wn = wid >> 2;
    int rowBase = blockIdx.x * 128;
    int r = lane >> 2;
    int cq = (lane & 3) * 2;

    float acc[2][4][4];
#pragma unroll
    for (int mt = 0; mt < 2; ++mt)
#pragma unroll
        for (int nt = 0; nt < 4; ++nt)
#pragma unroll
            for (int i = 0; i < 4; ++i) acc[mt][nt][i] = 0.f;

    for (int kt = 0; kt < 512; kt += 64) {
#pragma unroll
        for (int i = 0; i < 8; ++i) {
            int idx = tid + i * 256;
            int row = idx >> 4, c4 = (idx & 15) * 4;
            int grow = rowBase + row;
            float4 v = make_float4(0.f, 0.f, 0.f, 0.f);
            if (grow < M) v = *(const float4*)(A + (size_t)grow * 512 + kt + c4);
            __half h0 = __float2half_rn(v.x), h1 = __float2half_rn(v.y);
            __half h2 = __float2half_rn(v.z), h3 = __float2half_rn(v.w);
            *(__half2*)&sAhi[row][c4]     = __halves2half2(h0, h1);
            *(__half2*)&sAhi[row][c4 + 2] = __halves2half2(h2, h3);
            *(__half2*)&sAlo[row][c4]     = __floats2half2_rn(v.x - __half2float(h0), v.y - __half2float(h1));
            *(__half2*)&sAlo[row][c4 + 2] = __floats2half2_rn(v.z - __half2float(h2), v.w - __half2float(h3));
        }
#pragma unroll
        for (int i = 0; i < 4; ++i) {
            int idx = tid + i * 256;
            int k = idx >> 4, n4 = (idx & 15) * 4;
            float4 v = *(const float4*)(B + (size_t)(kt + k) * 64 + n4);
            sB[n4 + 0][k] = __float2half_rn(v.x);
            sB[n4 + 1][k] = __float2half_rn(v.y);
            sB[n4 + 2][k] = __float2half_rn(v.z);
            sB[n4 + 3][k] = __float2half_rn(v.w);
        }
        __syncthreads();

#pragma unroll
        for (int ks = 0; ks < 4; ++ks) {
            int c = cq + ks * 16;
            uint32_t bh[4][2];
#pragma unroll
            for (int nt = 0; nt < 4; ++nt) {
                int col = wn * 32 + nt * 8 + r;
                bh[nt][0] = *(const uint32_t*)&sB[col][c];
                bh[nt][1] = *(const uint32_t*)&sB[col][c + 8];
            }
#pragma unroll
            for (int mt = 0; mt < 2; ++mt) {
                int m = wm * 32 + mt * 16;
                uint32_t ah0 = *(const uint32_t*)&sAhi[m + r][c];
                uint32_t ah1 = *(const uint32_t*)&sAhi[m + r + 8][c];
                uint32_t ah2 = *(const uint32_t*)&sAhi[m + r][c + 8];
                uint32_t ah3 = *(const uint32_t*)&sAhi[m + r + 8][c + 8];
                uint32_t al0 = *(const uint32_t*)&sAlo[m + r][c];
                uint32_t al1 = *(const uint32_t*)&sAlo[m + r + 8][c];
                uint32_t al2 = *(const uint32_t*)&sAlo[m + r][c + 8];
                uint32_t al3 = *(const uint32_t*)&sAlo[m + r + 8][c + 8];
#pragma unroll
                for (int nt = 0; nt < 4; ++nt) {
                    mma16816(acc[mt][nt], ah0, ah1, ah2, ah3, bh[nt][0], bh[nt][1]);
                    mma16816(acc[mt][nt], al0, al1, al2, al3, bh[nt][0], bh[nt][1]);
                }
            }
        }
        __syncthreads();
    }

#pragma unroll
    for (int mt = 0; mt < 2; ++mt) {
        int row0 = rowBase + wm * 32 + mt * 16 + r;
        int row1 = row0 + 8;
#pragma unroll
        for (int nt = 0; nt < 4; ++nt) {
            int col = wn * 32 + nt * 8 + cq;
            if (row0 < M)
                *(__half2*)(C + (size_t)row0 * 64 + col) =
                    __floats2half2_rn(acc[mt][nt][0], acc[mt][nt][1]);
            if (row1 < M)
                *(__half2*)(C + (size_t)row1 * 64 + col) =
                    __floats2half2_rn(acc[mt][nt][2], acc[mt][nt][3]);
        }
    }
}

// ---------------- fp16 gather helper (FFMA2, float2 accumulators) ------------
__device__ __forceinline__ void fma_half8(float2* acc, uint4 raw, float v) {
    float2 vv = make_float2(v, v);
    float2 f0 = __half22float2(*(__half2*)&raw.x);
    float2 f1 = __half22float2(*(((__half2*)&raw.x) + 1));
    float2 f2 = __half22float2(*(__half2*)&raw.z);
    float2 f3 = __half22float2(*(((__half2*)&raw.z) + 1));
    acc[0] = ffma2(vv, f0, acc[0]);
    acc[1] = ffma2(vv, f1, acc[1]);
    acc[2] = ffma2(vv, f2, acc[2]);
    acc[3] = ffma2(vv, f3, acc[3]);
}

// ---------------- SpMM stage: 2-edge unrolled gathers, warp per node ---------
template <int D, int GRP>
__device__ void spmm_stage(const __half* __restrict__ sup, const int* __restrict__ ecol,
                           const float* __restrict__ ev, const int* __restrict__ rp,
                           float* __restrict__ out, int n) {
    const int STRIDE = 32 / GRP;
    int tid = threadIdx.x, wid = tid >> 5, lane = tid & 31;
    int g = lane / GRP, sl = lane % GRP;
    int nwarps = gridDim.x * 8;
    for (int node = blockIdx.x * 8 + wid; node < n; node += nwarps) {
        int s = rp[node], e = rp[node + 1];
        float2 acc[4];
#pragma unroll
        for (int i = 0; i < 4; ++i) acc[i] = make_float2(0.f, 0.f);
        int j = s + g;
        for (; j + STRIDE < e; j += 2 * STRIDE) {
            int   c0 = ecol[j];          float v0 = ev[j];
            int   c1 = ecol[j + STRIDE]; float v1 = ev[j + STRIDE];
            uint4 r0 = *(const uint4*)(sup + (size_t)c0 * D + sl * 8);
            uint4 r1 = *(const uint4*)(sup + (size_t)c1 * D + sl * 8);
            fma_half8(acc, r0, v0);
            fma_half8(acc, r1, v1);
        }
        if (j < e) {
            int c = ecol[j]; float v = ev[j];
            uint4 raw = *(const uint4*)(sup + (size_t)c * D + sl * 8);
            fma_half8(acc, raw, v);
        }
#pragma unroll
        for (int o = 16; o >= GRP; o >>= 1)
#pragma unroll
            for (int i = 0; i < 4; ++i) {
                acc[i].x += __shfl_down_sync(0xffffffffu, acc[i].x, o);
                acc[i].y += __shfl_down_sync(0xffffffffu, acc[i].y, o);
            }
        if (lane < GRP) {
            float* op = out + (size_t)node * D + lane * 8;
            *(float4*)op       = make_float4(acc[0].x, acc[0].y, acc[1].x, acc[1].y);
            *(float4*)(op + 4) = make_float4(acc[2].x, acc[2].y, acc[3].x, acc[3].y);
        }
    }
}

// ---------------- column stats stage -----------------------------------------
template <int D>
__device__ void col_stats_stage(const float* __restrict__ h, int n, int layer,
                                float* s_sum, float* s_sq) {
    const int S4 = D / 4;
    const int REPS = 256 / S4;
    int tid = threadIdx.x;
    if (tid < D) { s_sum[tid] = 0.f; s_sq[tid] = 0.f; }
    __syncthreads();
    int ch4 = tid % S4, rep = tid / S4;
    float4 s = make_float4(0.f, 0.f, 0.f, 0.f);
    float4 q = make_float4(0.f, 0.f, 0.f, 0.f);
    for (int r = blockIdx.x * REPS + rep; r < n; r += gridDim.x * REPS) {
        float4 v = *(const float4*)(h + (size_t)r * D + ch4 * 4);
        s.x += v.x; s.y += v.y; s.z += v.z; s.w += v.w;
        q.x = fmaf(v.x, v.x, q.x); q.y = fmaf(v.y, v.y, q.y);
        q.z = fmaf(v.z, v.z, q.z); q.w = fmaf(v.w, v.w, q.w);
    }
    atomicAdd(&s_sum[ch4 * 4 + 0], s.x); atomicAdd(&s_sq[ch4 * 4 + 0], q.x);
    atomicAdd(&s_sum[ch4 * 4 + 1], s.y); atomicAdd(&s_sq[ch4 * 4 + 1], q.y);
    atomicAdd(&s_sum[ch4 * 4 + 2], s.z); atomicAdd(&s_sq[ch4 * 4 + 2], q.z);
    atomicAdd(&s_sum[ch4 * 4 + 3], s.w); atomicAdd(&s_sq[ch4 * 4 + 3], q.w);
    __syncthreads();
    if (tid < D) {
        atomicAdd(&g_stats[layer * 128 + tid], s_sum[tid]);
        atomicAdd(&g_stats[layer * 128 + 64 + tid], s_sq[tid]);
    }
    __syncthreads();
}

// ---------------- fused BN+ELU + small GEMM stage (shuffle broadcast) --------
template <int IN, int OUT>
__device__ void gemm_small_stage(const float* __restrict__ h, const float* __restrict__ W,
                                 const float* __restrict__ gamma, const float* __restrict__ beta,
                                 int layer, __half* __restrict__ out, int n,
                                 float* sWs, float* sc, float* sh) {
    int tid = threadIdx.x;
    for (int i = tid; i < IN * OUT; i += 256) sWs[i] = W[i];
    if (tid < IN) {
        float invn = 1.0f / (float)n;
        float mean = g_stats[layer * 128 + tid] * invn;
        float var  = g_stats[layer * 128 + 64 + tid] * invn - mean * mean;
        float k    = rsqrtf(var + 1e-5f) * gamma[tid];
        sc[tid] = k;
        sh[tid] = beta[tid] - mean * k;
    }
    __syncthreads();
    int wid = tid >> 5, lane = tid & 31;
    float scA = (lane < IN) ? sc[lane] : 0.f;
    float shA = (lane < IN) ? sh[lane] : 0.f;
    float scB = (IN == 64) ? sc[lane + 32] : 0.f;
    float shB = (IN == 64) ? sh[lane + 32] : 0.f;
    for (int node = blockIdx.x * 8 + wid; node < n; node += gridDim.x * 8) {
        const float* hr = h + (size_t)node * IN;
        float ya = 0.f, yb = 0.f;
        if (lane < IN) {
            float xv = hr[lane];
            ya = fmaf(xv, scA, shA);
            ya = ya > 0.f ? ya : (__expf(ya) - 1.0f);
        }
        if (IN == 64) {
            float xv = hr[lane + 32];
            yb = fmaf(xv, scB, shB);
            yb = yb > 0.f ? yb : (__expf(yb) - 1.0f);
        }
        float acc = 0.f;
        const int KA = (IN < 32) ? IN : 32;
#pragma unroll
        for (int k = 0; k < KA; ++k) {
            float yk = __shfl_sync(0xffffffffu, ya, k);
            acc = fmaf(yk, sWs[k * OUT + lane], acc);
        }
        if (IN == 64) {
#pragma unroll
            for (int k = 0; k < 32; ++k) {
                float yk = __shfl_sync(0xffffffffu, yb, k);
                acc = fmaf(yk, sWs[(k + 32) * OUT + lane], acc);
            }
        }
        if (lane < OUT) out[(size_t)node * OUT + lane] = __float2half_rn(acc);
    }
    __syncthreads();
}

// ---------------- THE persistent kernel: everything after gemm1 --------------
__global__ void __launch_bounds__(256, 6) fused_rest(
    __half* __restrict__ hH, float* __restrict__ hF,
    const int* __restrict__ ecol, const float* __restrict__ ev, const int* __restrict__ rp,
    const float* __restrict__ W2, const float* __restrict__ W3, const float* __restrict__ W4,
    const float* __restrict__ g1, const float* __restrict__ b1,
    const float* __restrict__ g2, const float* __restrict__ b2,
    const float* __restrict__ g3, const float* __restrict__ b3,
    float* __restrict__ out, int n) {
    __shared__ float sWs[64 * 32];
    __shared__ float sA[64], sB2[64];

    int tid = threadIdx.x;

    // S0: spmm64 (hH -> hF)
    spmm_stage<64, 8>(hH, ecol, ev, rp, hF, n);
    grid_barrier();

    // S1: stats layer0
    col_stats_stage<64>(hF, n, 0, sA, sB2);
    grid_barrier();

    // S2: bn0+elu+gemm 64->32  (hF -> hH)
    gemm_small_stage<64, 32>(hF, W2, g1, b1, 0, hH, n, sWs, sA, sB2);
    grid_barrier();

    // S3: spmm32 (hH -> hF)
    spmm_stage<32, 4>(hH, ecol, ev, rp, hF, n);
    grid_barrier();

    // S4: stats layer1
    col_stats_stage<32>(hF, n, 1, sA, sB2);
    grid_barrier();

    // S5: bn1+elu+gemm 32->16 (hF -> hH)
    gemm_small_stage<32, 16>(hF, W3, g2, b2, 1, hH, n, sWs, sA, sB2);
    grid_barrier();

    // S6: spmm16 (hH -> hF)
    spmm_stage<16, 2>(hH, ecol, ev, rp, hF, n);
    grid_barrier();

    // S7: stats layer2
    col_stats_stage<16>(hF, n, 2, sA, sB2);
    grid_barrier();

    // S8: bn2+elu (hF -> hH), elementwise
    {
        float invn = 1.0f / (float)n;
        for (int i = blockIdx.x * 256 + tid; i < n * 16; i += gridDim.x * 256) {
            int ch = i & 15;
            float mean = g_stats[256 + ch] * invn;
            float var  = g_stats[256 + 64 + ch] * invn - mean * mean;
            float k = rsqrtf(var + 1e-5f) * g3[ch];
            float y = fmaf(hF[i] - mean, k, b3[ch]);
            hH[i] = __float2half_rn(y > 0.f ? y : (__expf(y) - 1.0f));
        }
    }
    grid_barrier();

    // S9: FUSED final: spmm16 -> gemm(16->40) -> log_softmax (hH -> out)
    {
        for (int i = tid; i < 16 * 40; i += 256) sWs[i] = W4[i];
        __syncthreads();
        int wid = tid >> 5, lane = tid & 31;
        int g = lane >> 1, sl = lane & 1;       // GRP=2, STRIDE=16
        int nwarps = gridDim.x * 8;
        for (int node = blockIdx.x * 8 + wid; node < n; node += nwarps) {
            int s = rp[node], e = rp[node + 1];
            float2 acc[4];
#pragma unroll
            for (int i = 0; i < 4; ++i) acc[i] = make_float2(0.f, 0.f);
            int j = s + g;
            for (; j + 16 < e; j += 32) {
                int   c0 = ecol[j];      float v0 = ev[j];
                int   c1 = ecol[j + 16]; float v1 = ev[j + 16];
                uint4 r0 = *(const uint4*)(hH + (size_t)c0 * 16 + sl * 8);
                uint4 r1 = *(const uint4*)(hH + (size_t)c1 * 16 + sl * 8);
                fma_half8(acc, r0, v0);
                fma_half8(acc, r1, v1);
            }
            if (j < e) {
                int c = ecol[j]; float v = ev[j];
                uint4 raw = *(const uint4*)(hH + (size_t)c * 16 + sl * 8);
                fma_half8(acc, raw, v);
            }
#pragma unroll
            for (int o = 16; o >= 2; o >>= 1)
#pragma unroll
                for (int i = 0; i < 4; ++i) {
                    acc[i].x += __shfl_down_sync(0xffffffffu, acc[i].x, o);
                    acc[i].y += __shfl_down_sync(0xffffffffu, acc[i].y, o);
                }
            float acc0 = 0.f, acc1 = 0.f;
#pragma unroll
            for (int k = 0; k < 16; ++k) {
                float val = (k & 1) ? acc[(k & 7) >> 1].y : acc[(k & 7) >> 1].x;
                float yk = __shfl_sync(0xffffffffu, val, k >> 3);
                acc0 = fmaf(yk, sWs[k * 40 + lane], acc0);
                if (lane < 8) acc1 = fmaf(yk, sWs[k * 40 + 32 + lane], acc1);
            }
            float a1 = (lane < 8) ? acc1 : __int_as_float(0xff800000);
            float m = fmaxf(acc0, a1);
#pragma unroll
            for (int o = 16; o; o >>= 1) m = fmaxf(m, __shfl_xor_sync(0xffffffffu, m, o));
            float ssum = expf(acc0 - m) + ((lane < 8) ? expf(acc1 - m) : 0.f);
#pragma unroll
            for (int o = 16; o; o >>= 1) ssum += __shfl_xor_sync(0xffffffffu, ssum, o);
            float lse = logf(ssum) + m;
            out[(size_t)node * 40 + lane] = acc0 - lse;
            if (lane < 8) out[(size_t)node * 40 + 32 + lane] = acc1 - lse;
        }
    }
}

// ---------------- launch ------------------------------------------------------
static inline int dg(long long t, int b) { return (int)((t + b - 1) / b); }

extern "C" void kernel_launch(void* const* d_in, const int* in_sizes, int n_in,
                              void* d_out, int out_size) {
    const float* x    = (const float*)d_in[0];
    const int*   erow = (const int*)d_in[1];
    const int*   ecol = (const int*)d_in[2];
    const float* ev   = (const float*)d_in[3];
    const float* W1   = (const float*)d_in[4];
    const float* W2   = (const float*)d_in[5];
    const float* W3   = (const float*)d_in[6];
    const float* W4   = (const float*)d_in[7];
    const float* g1   = (const float*)d_in[8];
    const float* b1   = (const float*)d_in[9];
    const float* g2   = (const float*)d_in[10];
    const float* b2   = (const float*)d_in[11];
    const float* g3   = (const float*)d_in[12];
    const float* b3   = (const float*)d_in[13];

    int n = in_sizes[0] / IN_DIM;
    int E = in_sizes[1];
    float* out = (float*)d_out;

    __half* hH; float* hF; int* rp;
    cudaGetSymbolAddress((void**)&hH, g_bufH);
    cudaGetSymbolAddress((void**)&hF, g_bufF);
    cudaGetSymbolAddress((void**)&rp, g_rp);

    const int PERS = 148 * 6;   // co-resident capacity at launch_bounds(256,6)

    int gb = dg(n, 128);
    int rb = dg(n + 1, 256);
    int grid1 = gb > rb ? gb : rb;

    gemm1_hmma<<<grid1, 256>>>(x, W1, hH, n, erow, E, rp);
    fused_rest<<<PERS, 256>>>(hH, hF, ecol, ev, rp, W2, W3, W4,
                              g1, b1, g2, b2, g3, b3, out, n);
}

// round 15
// speedup vs baseline: 1.9877x; 1.0494x over previous
#include <cuda_runtime.h>
#include <cuda_fp16.h>
#include <cstdint>
#include <math.h>

#define MAXN 100000
#define IN_DIM 512

// ---------------- scratch ----------------------------------------------------
__device__ __half g_bufH[MAXN * 64];   // support matrices (gathered operand, fp16)
__device__ float  g_bufF[MAXN * 64];   // spmm outputs (fp32)
__device__ int    g_rp[MAXN + 1];
__device__ float  g_stats[384];        // 3 layers x (64 sum + 64 sumsq)
__device__ unsigned g_barCount = 0;    // grid barrier (monotonic gen -> replay-safe)
__device__ unsigned g_barGen   = 0;

// ---------------- grid barrier (persistent kernel, all blocks resident) ------
__device__ __forceinline__ void grid_barrier() {
    __threadfence();
    __syncthreads();
    if (threadIdx.x == 0) {
        volatile unsigned* vgen = &g_barGen;
        unsigned gen = *vgen;
        unsigned arrived = atomicAdd(&g_barCount, 1u) + 1u;
        if (arrived == gridDim.x) {
            g_barCount = 0;
            __threadfence();
            *vgen = gen + 1u;
        } else {
            while (*vgen == gen) __nanosleep(64);
        }
    }
    __syncthreads();
    __threadfence();
}

// ---------------- packed f32x2 FMA -------------------------------------------
__device__ __forceinline__ float2 ffma2(float2 a, float2 b, float2 c) {
    unsigned long long ua = *reinterpret_cast<unsigned long long*>(&a);
    unsigned long long ub = *reinterpret_cast<unsigned long long*>(&b);
    unsigned long long uc = *reinterpret_cast<unsigned long long*>(&c);
    unsigned long long ud;
    asm("fma.rn.f32x2 %0, %1, %2, %3;" : "=l"(ud) : "l"(ua), "l"(ub), "l"(uc));
    return *reinterpret_cast<float2*>(&ud);
}

// ---------------- HMMA m16n8k16 fp16 -> fp32 ---------------------------------
__device__ __forceinline__ void mma16816(float* c, uint32_t a0, uint32_t a1,
                                         uint32_t a2, uint32_t a3,
                                         uint32_t b0, uint32_t b1) {
    asm volatile(
        "mma.sync.aligned.m16n8k16.row.col.f32.f16.f16.f32 "
        "{%0,%1,%2,%3}, {%4,%5,%6,%7}, {%8,%9}, {%0,%1,%2,%3};"
        : "+f"(c[0]), "+f"(c[1]), "+f"(c[2]), "+f"(c[3])
        : "r"(a0), "r"(a1), "r"(a2), "r"(a3), "r"(b0), "r"(b1));
}

// ---------------- GEMM1 (single fp16 A) + rowptr build + stats zeroing -------
__global__ void __launch_bounds__(256, 4) gemm1_hmma(
    const float* __restrict__ A, const float* __restrict__ B,
    __half* __restrict__ C, int M,
    const int* __restrict__ erow, int E, int* __restrict__ rp) {
    __shared__ __half sA[128][72];
    __shared__ __half sB[64][72];      // transposed: [n][k]

    int tid = threadIdx.x;

    // prologue: rowptr binary searches + stats zeroing (stream-ordered, replay-safe)
    {
        int i = blockIdx.x * 256 + tid;
        if (i <= M) {
            int lo = 0, hi = E;
            while (lo < hi) { int mid = (lo + hi) >> 1; if (erow[mid] < i) lo = mid + 1; else hi = mid; }
            rp[i] = lo;
        }
        if (blockIdx.x == 0) {
            for (int k = tid; k < 384; k += 256) g_stats[k] = 0.f;
        }
    }

    int wid = tid >> 5, lane = tid & 31;
    int wm = wid & 3, wn = wid >> 2;
    int rowBase = blockIdx.x * 128;
    int r = lane >> 2;
    int cq = (lane & 3) * 2;

    float acc[2][4][4];
#pragma unroll
    for (int mt = 0; mt < 2; ++mt)
#pragma unroll
        for (int nt = 0; nt < 4; ++nt)
#pragma unroll
            for (int i = 0; i < 4; ++i) acc[mt][nt][i] = 0.f;

    for (int kt = 0; kt < 512; kt += 64) {
#pragma unroll
        for (int i = 0; i < 8; ++i) {
            int idx = tid + i * 256;
            int row = idx >> 4, c4 = (idx & 15) * 4;
            int grow = rowBase + row;
            float4 v = make_float4(0.f, 0.f, 0.f, 0.f);
            if (grow < M) v = *(const float4*)(A + (size_t)grow * 512 + kt + c4);
            *(__half2*)&sA[row][c4]     = __floats2half2_rn(v.x, v.y);
            *(__half2*)&sA[row][c4 + 2] = __floats2half2_rn(v.z, v.w);
        }
#pragma unroll
        for (int i = 0; i < 4; ++i) {
            int idx = tid + i * 256;
            int k = idx >> 4, n4 = (idx & 15) * 4;
            float4 v = *(const float4*)(B + (size_t)(kt + k) * 64 + n4);
            sB[n4 + 0][k] = __float2half_rn(v.x);
            sB[n4 + 1][k] = __float2half_rn(v.y);
            sB[n4 + 2][k] = __float2half_rn(v.z);
            sB[n4 + 3][k] = __float2half_rn(v.w);
        }
        __syncthreads();

#pragma unroll
        for (int ks = 0; ks < 4; ++ks) {
            int c = cq + ks * 16;
            uint32_t bh[4][2];
#pragma unroll
            for (int nt = 0; nt < 4; ++nt) {
                int col = wn * 32 + nt * 8 + r;
                bh[nt][0] = *(const uint32_t*)&sB[col][c];
                bh[nt][1] = *(const uint32_t*)&sB[col][c + 8];
            }
#pragma unroll
            for (int mt = 0; mt < 2; ++mt) {
                int m = wm * 32 + mt * 16;
                uint32_t a0 = *(const uint32_t*)&sA[m + r][c];
                uint32_t a1 = *(const uint32_t*)&sA[m + r + 8][c];
                uint32_t a2 = *(const uint32_t*)&sA[m + r][c + 8];
                uint32_t a3 = *(const uint32_t*)&sA[m + r + 8][c + 8];
#pragma unroll
                for (int nt = 0; nt < 4; ++nt)
                    mma16816(acc[mt][nt], a0, a1, a2, a3, bh[nt][0], bh[nt][1]);
            }
        }
        __syncthreads();
    }

#pragma unroll
    for (int mt = 0; mt < 2; ++mt) {
        int row0 = rowBase + wm * 32 + mt * 16 + r;
        int row1 = row0 + 8;
#pragma unroll
        for (int nt = 0; nt < 4; ++nt) {
            int col = wn * 32 + nt * 8 + cq;
            if (row0 < M)
                *(__half2*)(C + (size_t)row0 * 64 + col) =
                    __floats2half2_rn(acc[mt][nt][0], acc[mt][nt][1]);
            if (row1 < M)
                *(__half2*)(C + (size_t)row1 * 64 + col) =
                    __floats2half2_rn(acc[mt][nt][2], acc[mt][nt][3]);
        }
    }
}

// ---------------- fp16 gather helper (FFMA2, float2 accumulators) ------------
__device__ __forceinline__ void fma_half8(float2* acc, uint4 raw, float v) {
    float2 vv = make_float2(v, v);
    float2 f0 = __half22float2(*(__half2*)&raw.x);
    float2 f1 = __half22float2(*(((__half2*)&raw.x) + 1));
    float2 f2 = __half22float2(*(__half2*)&raw.z);
    float2 f3 = __half22float2(*(((__half2*)&raw.z) + 1));
    acc[0] = ffma2(vv, f0, acc[0]);
    acc[1] = ffma2(vv, f1, acc[1]);
    acc[2] = ffma2(vv, f2, acc[2]);
    acc[3] = ffma2(vv, f3, acc[3]);
}

// ---------------- SpMM stage with optional fused stats -----------------------
// Stats: per-warp non-atomic smem accumulators (lane k owns channels 8k..8k+7),
// flushed once per block via global atomics. sStats needs 8 * 2D floats.
template <int D, int GRP, bool STATS>
__device__ void spmm_stage(const __half* __restrict__ sup, const int* __restrict__ ecol,
                           const float* __restrict__ ev, const int* __restrict__ rp,
                           float* __restrict__ out, int n, int layer, float* sStats) {
    const int STRIDE = 32 / GRP;
    int tid = threadIdx.x, wid = tid >> 5, lane = tid & 31;
    int g = lane / GRP, sl = lane % GRP;
    if (STATS) {
        for (int i = tid; i < 8 * 2 * D; i += 256) sStats[i] = 0.f;
        __syncthreads();
    }
    float* myStats = sStats + wid * 2 * D;
    int nwarps = gridDim.x * 8;
    for (int node = blockIdx.x * 8 + wid; node < n; node += nwarps) {
        int s = rp[node], e = rp[node + 1];
        float2 acc[4];
#pragma unroll
        for (int i = 0; i < 4; ++i) acc[i] = make_float2(0.f, 0.f);
        int j = s + g;
        for (; j + STRIDE < e; j += 2 * STRIDE) {
            int   c0 = ecol[j];          float v0 = ev[j];
            int   c1 = ecol[j + STRIDE]; float v1 = ev[j + STRIDE];
            uint4 r0 = *(const uint4*)(sup + (size_t)c0 * D + sl * 8);
            uint4 r1 = *(const uint4*)(sup + (size_t)c1 * D + sl * 8);
            fma_half8(acc, r0, v0);
            fma_half8(acc, r1, v1);
        }
        if (j < e) {
            int c = ecol[j]; float v = ev[j];
            uint4 raw = *(const uint4*)(sup + (size_t)c * D + sl * 8);
            fma_half8(acc, raw, v);
        }
#pragma unroll
        for (int o = 16; o >= GRP; o >>= 1)
#pragma unroll
            for (int i = 0; i < 4; ++i) {
                acc[i].x += __shfl_down_sync(0xffffffffu, acc[i].x, o);
                acc[i].y += __shfl_down_sync(0xffffffffu, acc[i].y, o);
            }
        if (lane < GRP) {
            float* op = out + (size_t)node * D + lane * 8;
            *(float4*)op       = make_float4(acc[0].x, acc[0].y, acc[1].x, acc[1].y);
            *(float4*)(op + 4) = make_float4(acc[2].x, acc[2].y, acc[3].x, acc[3].y);
            if (STATS) {
                float* ms = myStats + lane * 8;
                float* mq = myStats + D + lane * 8;
#pragma unroll
                for (int i = 0; i < 4; ++i) {
                    float vx = acc[i].x, vy = acc[i].y;
                    ms[2 * i + 0] += vx; mq[2 * i + 0] = fmaf(vx, vx, mq[2 * i + 0]);
                    ms[2 * i + 1] += vy; mq[2 * i + 1] = fmaf(vy, vy, mq[2 * i + 1]);
                }
            }
        }
    }
    if (STATS) {
        __syncthreads();
        for (int i = tid; i < 2 * D; i += 256) {
            float s = 0.f;
#pragma unroll
            for (int w = 0; w < 8; ++w) s += sStats[w * 2 * D + i];
            int ch  = (i < D) ? i : (i - D);
            int off = (i < D) ? 0 : 64;
            atomicAdd(&g_stats[layer * 128 + off + ch], s);
        }
        __syncthreads();
    }
}

// ---------------- fused BN+ELU + small GEMM stage (shuffle broadcast) --------
template <int IN, int OUT>
__device__ void gemm_small_stage(const float* __restrict__ h, const float* __restrict__ W,
                                 const float* __restrict__ gamma, const float* __restrict__ beta,
                                 int layer, __half* __restrict__ out, int n,
                                 float* sWs, float* sc, float* sh) {
    int tid = threadIdx.x;
    for (int i = tid; i < IN * OUT; i += 256) sWs[i] = W[i];
    if (tid < IN) {
        float invn = 1.0f / (float)n;
        float mean = g_stats[layer * 128 + tid] * invn;
        float var  = g_stats[layer * 128 + 64 + tid] * invn - mean * mean;
        float k    = rsqrtf(var + 1e-5f) * gamma[tid];
        sc[tid] = k;
        sh[tid] = beta[tid] - mean * k;
    }
    __syncthreads();
    int wid = tid >> 5, lane = tid & 31;
    float scA = (lane < IN) ? sc[lane] : 0.f;
    float shA = (lane < IN) ? sh[lane] : 0.f;
    float scB = (IN == 64) ? sc[lane + 32] : 0.f;
    float shB = (IN == 64) ? sh[lane + 32] : 0.f;
    for (int node = blockIdx.x * 8 + wid; node < n; node += gridDim.x * 8) {
        const float* hr = h + (size_t)node * IN;
        float ya = 0.f, yb = 0.f;
        if (lane < IN) {
            float xv = hr[lane];
            ya = fmaf(xv, scA, shA);
            ya = ya > 0.f ? ya : (__expf(ya) - 1.0f);
        }
        if (IN == 64) {
            float xv = hr[lane + 32];
            yb = fmaf(xv, scB, shB);
            yb = yb > 0.f ? yb : (__expf(yb) - 1.0f);
        }
        float acc = 0.f;
        const int KA = (IN < 32) ? IN : 32;
#pragma unroll
        for (int k = 0; k < KA; ++k) {
            float yk = __shfl_sync(0xffffffffu, ya, k);
            acc = fmaf(yk, sWs[k * OUT + lane], acc);
        }
        if (IN == 64) {
#pragma unroll
            for (int k = 0; k < 32; ++k) {
                float yk = __shfl_sync(0xffffffffu, yb, k);
                acc = fmaf(yk, sWs[(k + 32) * OUT + lane], acc);
            }
        }
        if (lane < OUT) out[(size_t)node * OUT + lane] = __float2half_rn(acc);
    }
    __syncthreads();
}

// ---------------- THE persistent kernel: everything after gemm1 --------------
__global__ void __launch_bounds__(256, 6) fused_rest(
    __half* __restrict__ hH, float* __restrict__ hF,
    const int* __restrict__ ecol, const float* __restrict__ ev, const int* __restrict__ rp,
    const float* __restrict__ W2, const float* __restrict__ W3, const float* __restrict__ W4,
    const float* __restrict__ g1, const float* __restrict__ b1,
    const float* __restrict__ g2, const float* __restrict__ b2,
    const float* __restrict__ g3, const float* __restrict__ b3,
    float* __restrict__ out, int n) {
    __shared__ float sWs[64 * 32];     // weights OR per-warp stats (stage-disjoint)
    __shared__ float sA[64], sB2[64];

    int tid = threadIdx.x;

    // S0: spmm64 + stats0 (hH -> hF)
    spmm_stage<64, 8, true>(hH, ecol, ev, rp, hF, n, 0, sWs);
    grid_barrier();

    // S1: bn0+elu+gemm 64->32  (hF -> hH)
    gemm_small_stage<64, 32>(hF, W2, g1, b1, 0, hH, n, sWs, sA, sB2);
    grid_barrier();

    // S2: spmm32 + stats1 (hH -> hF)
    spmm_stage<32, 4, true>(hH, ecol, ev, rp, hF, n, 1, sWs);
    grid_barrier();

    // S3: bn1+elu+gemm 32->16 (hF -> hH)
    gemm_small_stage<32, 16>(hF, W3, g2, b2, 1, hH, n, sWs, sA, sB2);
    grid_barrier();

    // S4: spmm16 + stats2 (hH -> hF)
    spmm_stage<16, 2, true>(hH, ecol, ev, rp, hF, n, 2, sWs);
    grid_barrier();

    // S5: bn2+elu (hF -> hH), elementwise
    {
        float invn = 1.0f / (float)n;
        for (int i = blockIdx.x * 256 + tid; i < n * 16; i += gridDim.x * 256) {
            int ch = i & 15;
            float mean = g_stats[256 + ch] * invn;
            float var  = g_stats[256 + 64 + ch] * invn - mean * mean;
            float k = rsqrtf(var + 1e-5f) * g3[ch];
            float y = fmaf(hF[i] - mean, k, b3[ch]);
            hH[i] = __float2half_rn(y > 0.f ? y : (__expf(y) - 1.0f));
        }
    }
    grid_barrier();

    // S6: FUSED final: spmm16 -> gemm(16->40) -> log_softmax (hH -> out)
    {
        for (int i = tid; i < 16 * 40; i += 256) sWs[i] = W4[i];
        __syncthreads();
        int wid = tid >> 5, lane = tid & 31;
        int g = lane >> 1, sl = lane & 1;       // GRP=2, STRIDE=16
        int nwarps = gridDim.x * 8;
        for (int node = blockIdx.x * 8 + wid; node < n; node += nwarps) {
            int s = rp[node], e = rp[node + 1];
            float2 acc[4];
#pragma unroll
            for (int i = 0; i < 4; ++i) acc[i] = make_float2(0.f, 0.f);
            int j = s + g;
            for (; j + 16 < e; j += 32) {
                int   c0 = ecol[j];      float v0 = ev[j];
                int   c1 = ecol[j + 16]; float v1 = ev[j + 16];
                uint4 r0 = *(const uint4*)(hH + (size_t)c0 * 16 + sl * 8);
                uint4 r1 = *(const uint4*)(hH + (size_t)c1 * 16 + sl * 8);
                fma_half8(acc, r0, v0);
                fma_half8(acc, r1, v1);
            }
            if (j < e) {
                int c = ecol[j]; float v = ev[j];
                uint4 raw = *(const uint4*)(hH + (size_t)c * 16 + sl * 8);
                fma_half8(acc, raw, v);
            }
#pragma unroll
            for (int o = 16; o >= 2; o >>= 1)
#pragma unroll
                for (int i = 0; i < 4; ++i) {
                    acc[i].x += __shfl_down_sync(0xffffffffu, acc[i].x, o);
                    acc[i].y += __shfl_down_sync(0xffffffffu, acc[i].y, o);
                }
            float acc0 = 0.f, acc1 = 0.f;
#pragma unroll
            for (int k = 0; k < 16; ++k) {
                float val = (k & 1) ? acc[(k & 7) >> 1].y : acc[(k & 7) >> 1].x;
                float yk = __shfl_sync(0xffffffffu, val, k >> 3);
                acc0 = fmaf(yk, sWs[k * 40 + lane], acc0);
                if (lane < 8) acc1 = fmaf(yk, sWs[k * 40 + 32 + lane], acc1);
            }
            float a1 = (lane < 8) ? acc1 : __int_as_float(0xff800000);
            float m = fmaxf(acc0, a1);
#pragma unroll
            for (int o = 16; o; o >>= 1) m = fmaxf(m, __shfl_xor_sync(0xffffffffu, m, o));
            float ssum = expf(acc0 - m) + ((lane < 8) ? expf(acc1 - m) : 0.f);
#pragma unroll
            for (int o = 16; o; o >>= 1) ssum += __shfl_xor_sync(0xffffffffu, ssum, o);
            float lse = logf(ssum) + m;
            out[(size_t)node * 40 + lane] = acc0 - lse;
            if (lane < 8) out[(size_t)node * 40 + 32 + lane] = acc1 - lse;
        }
    }
}

// ---------------- launch ------------------------------------------------------
static inline int dg(long long t, int b) { return (int)((t + b - 1) / b); }

extern "C" void kernel_launch(void* const* d_in, const int* in_sizes, int n_in,
                              void* d_out, int out_size) {
    const float* x    = (const float*)d_in[0];
    const int*   erow = (const int*)d_in[1];
    const int*   ecol = (const int*)d_in[2];
    const float* ev   = (const float*)d_in[3];
    const float* W1   = (const float*)d_in[4];
    const float* W2   = (const float*)d_in[5];
    const float* W3   = (const float*)d_in[6];
    const float* W4   = (const float*)d_in[7];
    const float* g1   = (const float*)d_in[8];
    const float* b1   = (const float*)d_in[9];
    const float* g2   = (const float*)d_in[10];
    const float* b2   = (const float*)d_in[11];
    const float* g3   = (const float*)d_in[12];
    const float* b3   = (const float*)d_in[13];

    int n = in_sizes[0] / IN_DIM;
    int E = in_sizes[1];
    float* out = (float*)d_out;

    __half* hH; float* hF; int* rp;
    cudaGetSymbolAddress((void**)&hH, g_bufH);
    cudaGetSymbolAddress((void**)&hF, g_bufF);
    cudaGetSymbolAddress((void**)&rp, g_rp);

    const int PERS = 148 * 6;   // co-resident capacity at launch_bounds(256,6)

    int gb = dg(n, 128);
    int rb = dg(n + 1, 256);
    int grid1 = gb > rb ? gb : rb;

    gemm1_hmma<<<grid1, 256>>>(x, W1, hH, n, erow, E, rp);
    fused_rest<<<PERS, 256>>>(hH, hF, ecol, ev, rp, W2, W3, W4,
                              g1, b1, g2, b2, g3, b3, out, n);
}